// round 9
// baseline (speedup 1.0000x reference)
#include <cuda_runtime.h>
#include <cuda_fp16.h>
#include <cstdint>
#include <cstddef>

// ---------------------------------------------------------------------------
#define BROWS   8192
#define CROWS   308
#define DIM     1024
#define CTXD    768
#define FFI     4096
#define SEQ     2048
#define TCTX    77
#define NHEADS  16
#define DHEAD   64

// ---------------------------------------------------------------------------
// Scratch
// ---------------------------------------------------------------------------
__device__ __half g_xnh[(size_t)BROWS * DIM];
__device__ __half g_qh [(size_t)BROWS * DIM];
__device__ __half g_kh [(size_t)BROWS * DIM];
__device__ __half g_vh [(size_t)BROWS * DIM];
__device__ __half g_ah [(size_t)BROWS * DIM];
__device__ __half g_ggh[(size_t)BROWS * FFI];
__device__ float  g_h  [(size_t)BROWS * DIM];

// half weights + context; wff1 column-interleaved (lin,gate)
#define OWQ1 0
#define OWK1 1048576
#define OWV1 2097152
#define OWO1 3145728
#define OWQ2 4194304
#define OWK2 5242880
#define OWV2 6029312
#define OWO2 6815744
#define OWF1 7864320
#define OWF2 16252928
#define OCTX 20447232
#define WHTOT 20683776
__device__ __half g_wh[WHTOT];
__device__ float  g_bf1[2 * FFI];   // permuted FF1 bias (fp32)

// ---------------------------------------------------------------------------
// helpers
// ---------------------------------------------------------------------------
__device__ __forceinline__ void mma_h(float c[4], const unsigned a[4], const unsigned b[2]) {
    asm volatile(
        "mma.sync.aligned.m16n8k16.row.col.f32.f16.f16.f32 "
        "{%0,%1,%2,%3}, {%4,%5,%6,%7}, {%8,%9}, {%0,%1,%2,%3};\n"
        : "+f"(c[0]), "+f"(c[1]), "+f"(c[2]), "+f"(c[3])
        : "r"(a[0]), "r"(a[1]), "r"(a[2]), "r"(a[3]), "r"(b[0]), "r"(b[1]));
}
__device__ __forceinline__ void ldsm_x4(unsigned r[4], uint32_t addr) {
    asm volatile("ldmatrix.sync.aligned.m8n8.x4.shared.b16 {%0,%1,%2,%3}, [%4];"
                 : "=r"(r[0]), "=r"(r[1]), "=r"(r[2]), "=r"(r[3]) : "r"(addr));
}
__device__ __forceinline__ void ldsm_x4_t(unsigned r[4], uint32_t addr) {
    asm volatile("ldmatrix.sync.aligned.m8n8.x4.trans.shared.b16 {%0,%1,%2,%3}, [%4];"
                 : "=r"(r[0]), "=r"(r[1]), "=r"(r[2]), "=r"(r[3]) : "r"(addr));
}
__device__ __forceinline__ void cpa16(uint32_t dst, const void* src, bool pred) {
    int sz = pred ? 16 : 0;
    asm volatile("cp.async.cg.shared.global [%0], [%1], 16, %2;\n"
                 :: "r"(dst), "l"(src), "r"(sz));
}
__device__ __forceinline__ void cpa_commit() { asm volatile("cp.async.commit_group;"); }
template<int N> __device__ __forceinline__ void cpa_wait() {
    asm volatile("cp.async.wait_group %0;" :: "n"(N));
}
__device__ __forceinline__ float gelu_tanh(float x) {
    const float x3 = x * x * x;
    return 0.5f * x * (1.f + tanhf(0.7978845608028654f * (x + 0.044715f * x3)));
}
__device__ __forceinline__ unsigned pack2(float a, float b) {
    __half2 h = __floats2half2_rn(a, b);
    return *reinterpret_cast<unsigned*>(&h);
}

// ---------------------------------------------------------------------------
// fp32 -> fp16 conversion pass (scale folds 0.125 into wq)
// ---------------------------------------------------------------------------
struct CJobs { const float* src[10]; __half* dst[10]; int n[10]; float scale[10]; };

__global__ __launch_bounds__(256) void conv_kernel(CJobs j) {
    const int job = blockIdx.y;
    const float* s = j.src[job];
    __half* d = j.dst[job];
    const int n = j.n[job];
    const float sc = j.scale[job];
    for (int i = (blockIdx.x * 256 + threadIdx.x) * 4; i < n; i += gridDim.x * 1024) {
        float4 v = *reinterpret_cast<const float4*>(s + i);
        uint2 u;
        u.x = pack2(v.x * sc, v.y * sc);
        u.y = pack2(v.z * sc, v.w * sc);
        *reinterpret_cast<uint2*>(d + i) = u;
    }
}

// Interleave wff1 columns: dst[k][2j]=lin col j, dst[k][2j+1]=gate col (j+FFI)
__global__ __launch_bounds__(256) void permute_ff1(
    const float* __restrict__ s, __half* __restrict__ d)
{
    const int k = blockIdx.y;
    const int j = blockIdx.x * 256 + threadIdx.x;
    const float lin = s[(size_t)k * (2 * FFI) + j];
    const float gt  = s[(size_t)k * (2 * FFI) + FFI + j];
    unsigned u = pack2(lin, gt);
    *reinterpret_cast<unsigned*>(d + (size_t)k * (2 * FFI) + 2 * j) = u;
}

__global__ __launch_bounds__(256) void permute_bias_ff1(
    const float* __restrict__ s, float* __restrict__ d)
{
    const int j = blockIdx.x * 256 + threadIdx.x;
    float2 v; v.x = s[j]; v.y = s[FFI + j];
    *reinterpret_cast<float2*>(d + 2 * j) = v;
}

// ---------------------------------------------------------------------------
// LayerNorm: fp32 in, fp16 out
// ---------------------------------------------------------------------------
__global__ __launch_bounds__(256) void ln_kernel(
    const float* __restrict__ x, __half* __restrict__ y,
    const float* __restrict__ gam, const float* __restrict__ bet)
{
    __shared__ float red[16];
    const int row = blockIdx.x;
    const int t = threadIdx.x;
    const float4 xv = reinterpret_cast<const float4*>(x + (size_t)row * DIM)[t];

    float s  = xv.x + xv.y + xv.z + xv.w;
    float sq = xv.x*xv.x + xv.y*xv.y + xv.z*xv.z + xv.w*xv.w;
    #pragma unroll
    for (int w = 16; w > 0; w >>= 1) {
        s  += __shfl_xor_sync(0xffffffffu, s,  w);
        sq += __shfl_xor_sync(0xffffffffu, sq, w);
    }
    const int wid = t >> 5, lid = t & 31;
    if (lid == 0) { red[wid] = s; red[8 + wid] = sq; }
    __syncthreads();
    if (t < 32) {
        float a  = (lid < 8) ? red[lid]     : 0.f;
        float aq = (lid < 8) ? red[8 + lid] : 0.f;
        #pragma unroll
        for (int w = 4; w > 0; w >>= 1) {
            a  += __shfl_xor_sync(0xffffffffu, a,  w);
            aq += __shfl_xor_sync(0xffffffffu, aq, w);
        }
        if (lid == 0) { red[0] = a; red[8] = aq; }
    }
    __syncthreads();
    const float mean = red[0] * (1.f / DIM);
    const float var  = red[8] * (1.f / DIM) - mean * mean;
    const float inv  = rsqrtf(var + 1e-5f);

    const float4 gv = reinterpret_cast<const float4*>(gam)[t];
    const float4 bv = reinterpret_cast<const float4*>(bet)[t];
    uint2 u;
    u.x = pack2((xv.x - mean) * inv * gv.x + bv.x, (xv.y - mean) * inv * gv.y + bv.y);
    u.y = pack2((xv.z - mean) * inv * gv.z + bv.z, (xv.w - mean) * inv * gv.w + bv.w);
    *reinterpret_cast<uint2*>(y + (size_t)row * DIM + t * 4) = u;
}

// ---------------------------------------------------------------------------
// fp16 GEMM v2: 128x128 CTA, 4 warps (2x2), warp tile 64x64, k-chunk 64,
// 3-stage cp.async, occ 2. mode: 0 = fp32 store, 1 = fp16 store, 2 = GEGLU
// ---------------------------------------------------------------------------
struct GemmB {
    const __half* W[3];
    const float* bias[3];
    const float* res[3];
    float* Cf[3];
    __half* Ch[3];
};

#define NSTG 3
#define AS_B 16384                 // A stage bytes (128 rows * 128B)
#define BS_B 16384                 // B stage bytes (64 rows * 256B)
#define GEMM_SMEM (NSTG * (AS_B + BS_B))   // 98304

__global__ __launch_bounds__(128, 2) void gemm_h(
    const __half* __restrict__ A, GemmB gb, int M, int N, int K, int mode)
{
    extern __shared__ char smc[];
    const int z = blockIdx.z;
    const __half* W   = gb.W[z];
    const float* bias = gb.bias[z];
    const float* res  = gb.res[z];
    float* Cf         = gb.Cf[z];
    __half* Ch        = gb.Ch[z];

    const int tid = threadIdx.x, warp = tid >> 5, lane = tid & 31;
    const int grp = lane >> 2, tig = lane & 3;
    const int wm = (warp & 1) * 64, wn = (warp >> 1) * 64;
    const int m0 = blockIdx.y << 7, n0 = blockIdx.x << 7;

    const uint32_t smem_u = (uint32_t)__cvta_generic_to_shared(smc);

    auto issue = [&](int ch, int slot) {
        const int k0 = ch << 6;
        const uint32_t ab = smem_u + slot * AS_B;
        #pragma unroll
        for (int i = 0; i < 8; i++) {
            const int idx = tid + i * 128;
            const int row = idx >> 3, c = idx & 7;
            int gr = m0 + row; if (gr >= M) gr = M - 1;
            cpa16(ab + row * 128 + ((c ^ (row & 7)) << 4),
                  A + (size_t)gr * K + k0 + c * 8, true);
        }
        const uint32_t bb = smem_u + NSTG * AS_B + slot * BS_B;
        #pragma unroll
        for (int i = 0; i < 8; i++) {
            const int idx = tid + i * 128;
            const int row = idx >> 4, c = idx & 15;
            cpa16(bb + row * 256 + ((c ^ (row & 7)) << 4),
                  W + (size_t)(k0 + row) * N + n0 + c * 8, true);
        }
        cpa_commit();
    };

    float acc[4][8][4];
    #pragma unroll
    for (int i = 0; i < 4; i++)
        #pragma unroll
        for (int j = 0; j < 8; j++)
            #pragma unroll
            for (int r = 0; r < 4; r++) acc[i][j][r] = 0.f;

    const int nch = K >> 6;
    issue(0, 0); issue(1, 1);

    for (int it = 0; it < nch; it++) {
        if (it + 1 < nch) cpa_wait<1>(); else cpa_wait<0>();
        __syncthreads();
        if (it + 2 < nch) issue(it + 2, (it + 2) % 3);

        const int slot = it % 3;
        const uint32_t ab = smem_u + slot * AS_B;
        const uint32_t bb = smem_u + NSTG * AS_B + slot * BS_B;

        #pragma unroll
        for (int ks = 0; ks < 4; ks++) {
            unsigned a[4][4];
            #pragma unroll
            for (int mi = 0; mi < 4; mi++) {
                const int row = wm + mi * 16 + (lane & 15);
                const int ch = ks * 2 + (lane >> 4);
                ldsm_x4(a[mi], ab + row * 128 + ((ch ^ (row & 7)) << 4));
            }
            unsigned b[4][4];
            #pragma unroll
            for (int njp = 0; njp < 4; njp++) {
                const int krow = ks * 16 + (lane & 15);
                const int cn = (wn >> 3) + njp * 2 + (lane >> 4);
                ldsm_x4_t(b[njp], bb + krow * 256 + ((cn ^ (krow & 7)) << 4));
            }
            #pragma unroll
            for (int mi = 0; mi < 4; mi++)
                #pragma unroll
                for (int njp = 0; njp < 4; njp++) {
                    mma_h(acc[mi][njp * 2 + 0], a[mi], b[njp] + 0);
                    mma_h(acc[mi][njp * 2 + 1], a[mi], b[njp] + 2);
                }
        }
        __syncthreads();
    }

    #pragma unroll
    for (int mi = 0; mi < 4; mi++) {
        #pragma unroll
        for (int half = 0; half < 2; half++) {
            const int r = m0 + wm + mi * 16 + grp + half * 8;
            if (r >= M) continue;
            #pragma unroll
            for (int nj = 0; nj < 8; nj++) {
                const int c = n0 + wn + nj * 8 + tig * 2;
                float2 v;
                v.x = acc[mi][nj][half * 2 + 0];
                v.y = acc[mi][nj][half * 2 + 1];
                if (bias) { v.x += bias[c]; v.y += bias[c + 1]; }
                if (mode == 2) {
                    Ch[(size_t)r * FFI + (c >> 1)] = __float2half_rn(v.x * gelu_tanh(v.y));
                } else if (mode == 1) {
                    unsigned u = pack2(v.x, v.y);
                    *reinterpret_cast<unsigned*>(Ch + (size_t)r * N + c) = u;
                } else {
                    if (res) {
                        const float2 rv =
                            *reinterpret_cast<const float2*>(res + (size_t)r * N + c);
                        v.x += rv.x; v.y += rv.y;
                    }
                    *reinterpret_cast<float2*>(Cf + (size_t)r * N + c) = v;
                }
            }
        }
    }
}

// ---------------------------------------------------------------------------
// fp16 flash attention: 4 warps, 128 q/CTA, 32 q/warp (2 m16 tiles), kt=64.
// smem: Qs/Ps 16KB @0 ; Ks 2x8KB @16384 ; Vs 2x8KB @32768  (total 48KB)
// ---------------------------------------------------------------------------
#define ATTN_SMEM 49152

__global__ __launch_bounds__(128, 2) void attn_h(
    const __half* __restrict__ Q, const __half* __restrict__ K,
    const __half* __restrict__ V, __half* __restrict__ O, int Sq, int Sk)
{
    extern __shared__ char smc[];
    const int tid = threadIdx.x, warp = tid >> 5, lane = tid & 31;
    const int grp = lane >> 2, tig = lane & 3;
    const int h = blockIdx.y, b = blockIdx.z;
    const int q0 = blockIdx.x * 128;
    const size_t qoff = (size_t)b * Sq * DIM + (size_t)h * DHEAD;
    const size_t koff = (size_t)b * Sk * DIM + (size_t)h * DHEAD;
    const int rbase = warp * 32;

    const uint32_t smem_u = (uint32_t)__cvta_generic_to_shared(smc);
    const uint32_t ks_u = smem_u + 16384;
    const uint32_t vs_u = smem_u + 32768;

    auto issue_kv = [&](int kt, int slot) {
        #pragma unroll
        for (int i = 0; i < 4; i++) {
            const int c = tid + i * 128;
            const int row = c >> 3, nc = c & 7;
            const int gr = kt * 64 + row;
            const bool ok = gr < Sk;
            const int grc = ok ? gr : 0;
            cpa16(ks_u + slot * 8192 + row * 128 + ((nc ^ (row & 7)) << 4),
                  K + koff + (size_t)grc * DIM + nc * 8, ok);
        }
        #pragma unroll
        for (int i = 0; i < 4; i++) {
            const int c = tid + i * 128;
            const int row = c >> 3, nc = c & 7;
            const int gr = kt * 64 + row;
            const bool ok = gr < Sk;
            const int grc = ok ? gr : 0;
            cpa16(vs_u + slot * 8192 + row * 128 + ((nc ^ (row & 7)) << 4),
                  V + koff + (size_t)grc * DIM + nc * 8, ok);
        }
        cpa_commit();
    };

    // Q tile load (scale pre-folded into wq)
    #pragma unroll
    for (int i = 0; i < 8; i++) {
        const int c = tid + i * 128;
        const int row = c >> 3, nc = c & 7;
        cpa16(smem_u + row * 128 + ((nc ^ (row & 7)) << 4),
              Q + qoff + (size_t)(q0 + row) * DIM + nc * 8, true);
    }
    cpa_commit();
    issue_kv(0, 0);

    unsigned qa[2][4][4];
    float o[2][8][4];
    #pragma unroll
    for (int t = 0; t < 2; t++)
        #pragma unroll
        for (int d = 0; d < 8; d++)
            #pragma unroll
            for (int r = 0; r < 4; r++) o[t][d][r] = 0.f;
    float mxA[2] = {-1e30f, -1e30f}, mxB[2] = {-1e30f, -1e30f};
    float lA[2] = {0.f, 0.f}, lB[2] = {0.f, 0.f};

    const int nkt = (Sk + 63) >> 6;
    for (int kt = 0; kt < nkt; kt++) {
        if (kt + 1 < nkt) { issue_kv(kt + 1, (kt + 1) & 1); cpa_wait<1>(); }
        else cpa_wait<0>();
        __syncthreads();

        if (kt == 0) {   // Q frags to registers (warp-private rows)
            #pragma unroll
            for (int t = 0; t < 2; t++)
                #pragma unroll
                for (int ks = 0; ks < 4; ks++) {
                    const int row = rbase + t * 16 + (lane & 15);
                    const int ch = ks * 2 + (lane >> 4);
                    ldsm_x4(qa[t][ks], smem_u + row * 128 + ((ch ^ (row & 7)) << 4));
                }
        }

        const uint32_t ksl = ks_u + (kt & 1) * 8192;
        const uint32_t vsl = vs_u + (kt & 1) * 8192;

        // ---- S = Q K^T ----
        float sc[2][8][4];
        #pragma unroll
        for (int t = 0; t < 2; t++)
            #pragma unroll
            for (int nj = 0; nj < 8; nj++)
                #pragma unroll
                for (int r = 0; r < 4; r++) sc[t][nj][r] = 0.f;

        #pragma unroll
        for (int ks = 0; ks < 4; ks++) {
            #pragma unroll
            for (int njp = 0; njp < 4; njp++) {
                unsigned kb[4];
                const int nrow = njp * 16 + (lane & 7) + (lane >> 4) * 8;
                const int kc = ks * 2 + ((lane >> 3) & 1);
                ldsm_x4(kb, ksl + nrow * 128 + ((kc ^ (nrow & 7)) << 4));
                #pragma unroll
                for (int t = 0; t < 2; t++) {
                    mma_h(sc[t][njp * 2 + 0], qa[t][ks], kb + 0);
                    mma_h(sc[t][njp * 2 + 1], qa[t][ks], kb + 2);
                }
            }
        }

        // mask padded keys
        if (kt * 64 + 64 > Sk) {
            #pragma unroll
            for (int t = 0; t < 2; t++)
                #pragma unroll
                for (int nj = 0; nj < 8; nj++) {
                    const int j = kt * 64 + nj * 8 + tig * 2;
                    if (j     >= Sk) { sc[t][nj][0] = -1e30f; sc[t][nj][2] = -1e30f; }
                    if (j + 1 >= Sk) { sc[t][nj][1] = -1e30f; sc[t][nj][3] = -1e30f; }
                }
        }

        // ---- online softmax ----
        #pragma unroll
        for (int t = 0; t < 2; t++) {
            float tm0 = -1e30f, tm1 = -1e30f;
            #pragma unroll
            for (int nj = 0; nj < 8; nj++) {
                tm0 = fmaxf(tm0, fmaxf(sc[t][nj][0], sc[t][nj][1]));
                tm1 = fmaxf(tm1, fmaxf(sc[t][nj][2], sc[t][nj][3]));
            }
            tm0 = fmaxf(tm0, __shfl_xor_sync(0xffffffffu, tm0, 1));
            tm0 = fmaxf(tm0, __shfl_xor_sync(0xffffffffu, tm0, 2));
            tm1 = fmaxf(tm1, __shfl_xor_sync(0xffffffffu, tm1, 1));
            tm1 = fmaxf(tm1, __shfl_xor_sync(0xffffffffu, tm1, 2));
            const float mn0 = fmaxf(mxA[t], tm0), mn1 = fmaxf(mxB[t], tm1);
            const float c0 = __expf(mxA[t] - mn0), c1 = __expf(mxB[t] - mn1);
            mxA[t] = mn0; mxB[t] = mn1;
            float s0 = 0.f, s1 = 0.f;
            #pragma unroll
            for (int nj = 0; nj < 8; nj++) {
                sc[t][nj][0] = __expf(sc[t][nj][0] - mn0);
                sc[t][nj][1] = __expf(sc[t][nj][1] - mn0);
                sc[t][nj][2] = __expf(sc[t][nj][2] - mn1);
                sc[t][nj][3] = __expf(sc[t][nj][3] - mn1);
                s0 += sc[t][nj][0] + sc[t][nj][1];
                s1 += sc[t][nj][2] + sc[t][nj][3];
            }
            s0 += __shfl_xor_sync(0xffffffffu, s0, 1);
            s0 += __shfl_xor_sync(0xffffffffu, s0, 2);
            s1 += __shfl_xor_sync(0xffffffffu, s1, 1);
            s1 += __shfl_xor_sync(0xffffffffu, s1, 2);
            lA[t] = lA[t] * c0 + s0;
            lB[t] = lB[t] * c1 + s1;
            #pragma unroll
            for (int d = 0; d < 8; d++) {
                o[t][d][0] *= c0; o[t][d][1] *= c0;
                o[t][d][2] *= c1; o[t][d][3] *= c1;
            }
        }

        // ---- publish P (half) to warp-private Ps rows (aliases Qs) ----
        #pragma unroll
        for (int t = 0; t < 2; t++)
            #pragma unroll
            for (int nj = 0; nj < 8; nj++) {
                const int r0 = rbase + t * 16 + grp;
                *reinterpret_cast<unsigned*>(smc + r0 * 128 +
                    ((nj ^ (r0 & 7)) << 4) + tig * 4) = pack2(sc[t][nj][0], sc[t][nj][1]);
                const int r1 = r0 + 8;
                *reinterpret_cast<unsigned*>(smc + r1 * 128 +
                    ((nj ^ (r1 & 7)) << 4) + tig * 4) = pack2(sc[t][nj][2], sc[t][nj][3]);
            }
        __syncwarp();

        // ---- O += P V ----
        #pragma unroll
        for (int kj = 0; kj < 4; kj++) {
            unsigned pa[2][4];
            #pragma unroll
            for (int t = 0; t < 2; t++) {
                const int row = rbase + t * 16 + (lane & 15);
                const int ch = kj * 2 + (lane >> 4);
                ldsm_x4(pa[t], smem_u + row * 128 + ((ch ^ (row & 7)) << 4));
            }
            #pragma unroll
            for (int dgp = 0; dgp < 4; dgp++) {
                unsigned vb[4];
                const int vrow = kj * 16 + (lane & 15);
                const int vc = dgp * 2 + (lane >> 4);
                ldsm_x4_t(vb, vsl + vrow * 128 + ((vc ^ (vrow & 7)) << 4));
                #pragma unroll
                for (int t = 0; t < 2; t++) {
                    mma_h(o[t][dgp * 2 + 0], pa[t], vb + 0);
                    mma_h(o[t][dgp * 2 + 1], pa[t], vb + 2);
                }
            }
        }
        __syncthreads();
    }

    #pragma unroll
    for (int t = 0; t < 2; t++) {
        const float i0 = 1.f / lA[t], i1 = 1.f / lB[t];
        const int row0 = q0 + rbase + t * 16 + grp;
        #pragma unroll
        for (int d = 0; d < 8; d++) {
            *reinterpret_cast<unsigned*>(O + qoff + (size_t)row0 * DIM + d * 8 + tig * 2) =
                pack2(o[t][d][0] * i0, o[t][d][1] * i0);
            *reinterpret_cast<unsigned*>(O + qoff + (size_t)(row0 + 8) * DIM + d * 8 + tig * 2) =
                pack2(o[t][d][2] * i1, o[t][d][3] * i1);
        }
    }
}

// ---------------------------------------------------------------------------
extern "C" void kernel_launch(void* const* d_in, const int* in_sizes, int n_in,
                              void* d_out, int out_size)
{
    const float* hs   = (const float*)d_in[0];
    const float* ctx  = (const float*)d_in[1];
    const float* wq1  = (const float*)d_in[2];
    const float* wk1  = (const float*)d_in[3];
    const float* wv1  = (const float*)d_in[4];
    const float* wo1  = (const float*)d_in[5];
    const float* bo1  = (const float*)d_in[6];
    const float* wq2  = (const float*)d_in[7];
    const float* wk2  = (const float*)d_in[8];
    const float* wv2  = (const float*)d_in[9];
    const float* wo2  = (const float*)d_in[10];
    const float* bo2  = (const float*)d_in[11];
    const float* wff1 = (const float*)d_in[12];
    const float* bff1 = (const float*)d_in[13];
    const float* wff2 = (const float*)d_in[14];
    const float* bff2 = (const float*)d_in[15];
    const float* ln1g = (const float*)d_in[16];
    const float* ln1b = (const float*)d_in[17];
    const float* ln2g = (const float*)d_in[18];
    const float* ln2b = (const float*)d_in[19];
    const float* ln3g = (const float*)d_in[20];
    const float* ln3b = (const float*)d_in[21];
    float* out = (float*)d_out;

    __half *xn, *q, *k, *v, *ah, *gg, *wh;
    float *h, *bf1;
    cudaGetSymbolAddress((void**)&xn,  g_xnh);
    cudaGetSymbolAddress((void**)&q,   g_qh);
    cudaGetSymbolAddress((void**)&k,   g_kh);
    cudaGetSymbolAddress((void**)&v,   g_vh);
    cudaGetSymbolAddress((void**)&ah,  g_ah);
    cudaGetSymbolAddress((void**)&gg,  g_ggh);
    cudaGetSymbolAddress((void**)&wh,  g_wh);
    cudaGetSymbolAddress((void**)&h,   g_h);
    cudaGetSymbolAddress((void**)&bf1, g_bf1);

    cudaFuncSetAttribute(gemm_h, cudaFuncAttributeMaxDynamicSharedMemorySize, GEMM_SMEM);
    cudaFuncSetAttribute(attn_h, cudaFuncAttributeMaxDynamicSharedMemorySize, ATTN_SMEM);

    // ---- convert weights + context to fp16 (0.125 folded into wq) ----
    CJobs cj;
    const float* srcs[10] = {wq1, wk1, wv1, wo1, wq2, wk2, wv2, wo2, wff2, ctx};
    const int    offs[10] = {OWQ1, OWK1, OWV1, OWO1, OWQ2, OWK2, OWV2, OWO2, OWF2, OCTX};
    const int    lens[10] = {1048576, 1048576, 1048576, 1048576, 1048576, 786432, 786432,
                             1048576, 4194304, 236544};
    for (int i = 0; i < 10; i++) {
        cj.src[i] = srcs[i]; cj.dst[i] = wh + offs[i]; cj.n[i] = lens[i];
        cj.scale[i] = (i == 0 || i == 4) ? 0.125f : 1.0f;
    }
    conv_kernel<<<dim3(512, 10), 256>>>(cj);
    permute_ff1<<<dim3(16, 1024), 256>>>(wff1, wh + OWF1);
    permute_bias_ff1<<<dim3(16), 256>>>(bff1, bf1);

    const dim3 blk(256);
    const dim3 gblk(128);
    const dim3 ablk(128);
    const dim3 g_attng(SEQ / 128, NHEADS, 4);

    GemmB gqkv{}, gwo1{}, gq2{}, gkv2{}, gwo2{}, gff1{}, gff2{};
    gqkv.W[0] = wh + OWQ1; gqkv.Ch[0] = q;
    gqkv.W[1] = wh + OWK1; gqkv.Ch[1] = k;
    gqkv.W[2] = wh + OWV1; gqkv.Ch[2] = v;
    gwo1.W[0] = wh + OWO1; gwo1.bias[0] = bo1; gwo1.res[0] = hs; gwo1.Cf[0] = h;
    gq2.W[0]  = wh + OWQ2; gq2.Ch[0]  = q;
    gkv2.W[0] = wh + OWK2; gkv2.Ch[0] = k;
    gkv2.W[1] = wh + OWV2; gkv2.Ch[1] = v;
    gwo2.W[0] = wh + OWO2; gwo2.bias[0] = bo2; gwo2.res[0] = h; gwo2.Cf[0] = h;
    gff1.W[0] = wh + OWF1; gff1.bias[0] = bf1; gff1.Ch[0] = gg;
    gff2.W[0] = wh + OWF2; gff2.bias[0] = bff2; gff2.res[0] = h; gff2.Cf[0] = out;

    // ---- self-attention ----
    ln_kernel<<<BROWS, blk>>>(hs, xn, ln1g, ln1b);
    gemm_h<<<dim3(8, 64, 3), gblk, GEMM_SMEM>>>(xn, gqkv, BROWS, DIM, DIM, 1);
    attn_h<<<g_attng, ablk, ATTN_SMEM>>>(q, k, v, ah, SEQ, SEQ);
    gemm_h<<<dim3(8, 64, 1), gblk, GEMM_SMEM>>>(ah, gwo1, BROWS, DIM, DIM, 0);

    // ---- cross-attention ----
    ln_kernel<<<BROWS, blk>>>(h, xn, ln2g, ln2b);
    gemm_h<<<dim3(8, 64, 1), gblk, GEMM_SMEM>>>(xn, gq2, BROWS, DIM, DIM, 1);
    gemm_h<<<dim3(8, 3, 2), gblk, GEMM_SMEM>>>(wh + OCTX, gkv2, CROWS, DIM, CTXD, 1);
    attn_h<<<g_attng, ablk, ATTN_SMEM>>>(q, k, v, ah, SEQ, TCTX);
    gemm_h<<<dim3(8, 64, 1), gblk, GEMM_SMEM>>>(ah, gwo2, BROWS, DIM, DIM, 0);

    // ---- GEGLU feed-forward (fused into FF1 epilogue) ----
    ln_kernel<<<BROWS, blk>>>(h, xn, ln3g, ln3b);
    gemm_h<<<dim3(64, 64, 1), gblk, GEMM_SMEM>>>(xn, gff1, BROWS, 2 * FFI, DIM, 2);
    gemm_h<<<dim3(8, 64, 1), gblk, GEMM_SMEM>>>(gg, gff2, BROWS, DIM, FFI, 0);
}

// round 10
// speedup vs baseline: 1.1232x; 1.1232x over previous
#include <cuda_runtime.h>
#include <cuda_fp16.h>
#include <cstdint>
#include <cstddef>

// ---------------------------------------------------------------------------
#define BROWS   8192
#define CROWS   308
#define DIM     1024
#define CTXD    768
#define FFI     4096
#define SEQ     2048
#define TCTX    77
#define NHEADS  16
#define DHEAD   64

// ---------------------------------------------------------------------------
// Scratch
// ---------------------------------------------------------------------------
__device__ __half g_xnh[(size_t)BROWS * DIM];
__device__ __half g_qh [(size_t)BROWS * DIM];
__device__ __half g_kh [(size_t)BROWS * DIM];
__device__ __half g_vh [(size_t)BROWS * DIM];
__device__ __half g_ah [(size_t)BROWS * DIM];
__device__ __half g_ggh[(size_t)BROWS * FFI];
__device__ float  g_h  [(size_t)BROWS * DIM];

// half weights + context; wff1 column-interleaved (lin,gate)
#define OWQ1 0
#define OWK1 1048576
#define OWV1 2097152
#define OWO1 3145728
#define OWQ2 4194304
#define OWK2 5242880
#define OWV2 6029312
#define OWO2 6815744
#define OWF1 7864320
#define OWF2 16252928
#define OCTX 20447232
#define WHTOT 20683776
__device__ __half g_wh[WHTOT];
__device__ float  g_bf1[2 * FFI];   // permuted FF1 bias (fp32)

// ---------------------------------------------------------------------------
// helpers
// ---------------------------------------------------------------------------
__device__ __forceinline__ void mma_h(float c[4], const unsigned a[4], const unsigned b[2]) {
    asm volatile(
        "mma.sync.aligned.m16n8k16.row.col.f32.f16.f16.f32 "
        "{%0,%1,%2,%3}, {%4,%5,%6,%7}, {%8,%9}, {%0,%1,%2,%3};\n"
        : "+f"(c[0]), "+f"(c[1]), "+f"(c[2]), "+f"(c[3])
        : "r"(a[0]), "r"(a[1]), "r"(a[2]), "r"(a[3]), "r"(b[0]), "r"(b[1]));
}
__device__ __forceinline__ void ldsm_x4(unsigned r[4], uint32_t addr) {
    asm volatile("ldmatrix.sync.aligned.m8n8.x4.shared.b16 {%0,%1,%2,%3}, [%4];"
                 : "=r"(r[0]), "=r"(r[1]), "=r"(r[2]), "=r"(r[3]) : "r"(addr));
}
__device__ __forceinline__ void ldsm_x4_t(unsigned r[4], uint32_t addr) {
    asm volatile("ldmatrix.sync.aligned.m8n8.x4.trans.shared.b16 {%0,%1,%2,%3}, [%4];"
                 : "=r"(r[0]), "=r"(r[1]), "=r"(r[2]), "=r"(r[3]) : "r"(addr));
}
__device__ __forceinline__ void cpa16(uint32_t dst, const void* src, bool pred) {
    int sz = pred ? 16 : 0;
    asm volatile("cp.async.cg.shared.global [%0], [%1], 16, %2;\n"
                 :: "r"(dst), "l"(src), "r"(sz));
}
__device__ __forceinline__ void cpa_commit() { asm volatile("cp.async.commit_group;"); }
template<int N> __device__ __forceinline__ void cpa_wait() {
    asm volatile("cp.async.wait_group %0;" :: "n"(N));
}
__device__ __forceinline__ float gelu_tanh(float x) {
    const float x3 = x * x * x;
    return 0.5f * x * (1.f + tanhf(0.7978845608028654f * (x + 0.044715f * x3)));
}
__device__ __forceinline__ unsigned pack2(float a, float b) {
    __half2 h = __floats2half2_rn(a, b);
    return *reinterpret_cast<unsigned*>(&h);
}

// ---------------------------------------------------------------------------
// fp32 -> fp16 conversion pass (scale folds 0.125 into wq)
// ---------------------------------------------------------------------------
struct CJobs { const float* src[10]; __half* dst[10]; int n[10]; float scale[10]; };

__global__ __launch_bounds__(256) void conv_kernel(CJobs j) {
    const int job = blockIdx.y;
    const float* s = j.src[job];
    __half* d = j.dst[job];
    const int n = j.n[job];
    const float sc = j.scale[job];
    for (int i = (blockIdx.x * 256 + threadIdx.x) * 4; i < n; i += gridDim.x * 1024) {
        float4 v = *reinterpret_cast<const float4*>(s + i);
        uint2 u;
        u.x = pack2(v.x * sc, v.y * sc);
        u.y = pack2(v.z * sc, v.w * sc);
        *reinterpret_cast<uint2*>(d + i) = u;
    }
}

// Interleave wff1 columns: dst[k][2j]=lin col j, dst[k][2j+1]=gate col (j+FFI)
__global__ __launch_bounds__(256) void permute_ff1(
    const float* __restrict__ s, __half* __restrict__ d)
{
    const int k = blockIdx.y;
    const int j = blockIdx.x * 256 + threadIdx.x;
    const float lin = s[(size_t)k * (2 * FFI) + j];
    const float gt  = s[(size_t)k * (2 * FFI) + FFI + j];
    unsigned u = pack2(lin, gt);
    *reinterpret_cast<unsigned*>(d + (size_t)k * (2 * FFI) + 2 * j) = u;
}

__global__ __launch_bounds__(256) void permute_bias_ff1(
    const float* __restrict__ s, float* __restrict__ d)
{
    const int j = blockIdx.x * 256 + threadIdx.x;
    float2 v; v.x = s[j]; v.y = s[FFI + j];
    *reinterpret_cast<float2*>(d + 2 * j) = v;
}

// ---------------------------------------------------------------------------
// LayerNorm: fp32 in, fp16 out
// ---------------------------------------------------------------------------
__global__ __launch_bounds__(256) void ln_kernel(
    const float* __restrict__ x, __half* __restrict__ y,
    const float* __restrict__ gam, const float* __restrict__ bet)
{
    __shared__ float red[16];
    const int row = blockIdx.x;
    const int t = threadIdx.x;
    const float4 xv = reinterpret_cast<const float4*>(x + (size_t)row * DIM)[t];

    float s  = xv.x + xv.y + xv.z + xv.w;
    float sq = xv.x*xv.x + xv.y*xv.y + xv.z*xv.z + xv.w*xv.w;
    #pragma unroll
    for (int w = 16; w > 0; w >>= 1) {
        s  += __shfl_xor_sync(0xffffffffu, s,  w);
        sq += __shfl_xor_sync(0xffffffffu, sq, w);
    }
    const int wid = t >> 5, lid = t & 31;
    if (lid == 0) { red[wid] = s; red[8 + wid] = sq; }
    __syncthreads();
    if (t < 32) {
        float a  = (lid < 8) ? red[lid]     : 0.f;
        float aq = (lid < 8) ? red[8 + lid] : 0.f;
        #pragma unroll
        for (int w = 4; w > 0; w >>= 1) {
            a  += __shfl_xor_sync(0xffffffffu, a,  w);
            aq += __shfl_xor_sync(0xffffffffu, aq, w);
        }
        if (lid == 0) { red[0] = a; red[8] = aq; }
    }
    __syncthreads();
    const float mean = red[0] * (1.f / DIM);
    const float var  = red[8] * (1.f / DIM) - mean * mean;
    const float inv  = rsqrtf(var + 1e-5f);

    const float4 gv = reinterpret_cast<const float4*>(gam)[t];
    const float4 bv = reinterpret_cast<const float4*>(bet)[t];
    uint2 u;
    u.x = pack2((xv.x - mean) * inv * gv.x + bv.x, (xv.y - mean) * inv * gv.y + bv.y);
    u.y = pack2((xv.z - mean) * inv * gv.z + bv.z, (xv.w - mean) * inv * gv.w + bv.w);
    *reinterpret_cast<uint2*>(y + (size_t)row * DIM + t * 4) = u;
}

// ---------------------------------------------------------------------------
// fp16 GEMM (R7 config): 128x128 CTA, 8 warps (2x4), warp tile 64x32,
// k-chunk 64, 3-stage cp.async, occ 2. ONE barrier per k-iteration.
// mode: 0 = fp32 store, 1 = fp16 store, 2 = GEGLU pairs -> Ch FFI-wide
// ---------------------------------------------------------------------------
struct GemmB {
    const __half* W[3];
    const float* bias[3];
    const float* res[3];
    float* Cf[3];
    __half* Ch[3];
};

#define NSTG 3
#define AS_B 16384                 // A stage bytes (128 rows * 128B)
#define BS_B 16384                 // B stage bytes (64 rows * 256B)
#define GEMM_SMEM (NSTG * (AS_B + BS_B))   // 98304

__global__ __launch_bounds__(256, 2) void gemm_h(
    const __half* __restrict__ A, GemmB gb, int M, int N, int K, int mode)
{
    extern __shared__ char smc[];
    const int z = blockIdx.z;
    const __half* W   = gb.W[z];
    const float* bias = gb.bias[z];
    const float* res  = gb.res[z];
    float* Cf         = gb.Cf[z];
    __half* Ch        = gb.Ch[z];

    const int tid = threadIdx.x, warp = tid >> 5, lane = tid & 31;
    const int grp = lane >> 2, tig = lane & 3;
    const int wm = (warp & 1) * 64, wn = (warp >> 1) * 32;
    const int m0 = blockIdx.y << 7, n0 = blockIdx.x << 7;

    const uint32_t smem_u = (uint32_t)__cvta_generic_to_shared(smc);

    auto issue = [&](int ch, int slot) {
        const int k0 = ch << 6;
        const uint32_t ab = smem_u + slot * AS_B;
        #pragma unroll
        for (int i = 0; i < 4; i++) {
            const int idx = tid + i * 256;
            const int row = idx >> 3, c = idx & 7;
            int gr = m0 + row; if (gr >= M) gr = M - 1;
            cpa16(ab + row * 128 + ((c ^ (row & 7)) << 4),
                  A + (size_t)gr * K + k0 + c * 8, true);
        }
        const uint32_t bb = smem_u + NSTG * AS_B + slot * BS_B;
        #pragma unroll
        for (int i = 0; i < 4; i++) {
            const int idx = tid + i * 256;
            const int row = idx >> 4, c = idx & 15;
            cpa16(bb + row * 256 + ((c ^ (row & 7)) << 4),
                  W + (size_t)(k0 + row) * N + n0 + c * 8, true);
        }
        cpa_commit();
    };

    float acc[4][4][4];
    #pragma unroll
    for (int i = 0; i < 4; i++)
        #pragma unroll
        for (int j = 0; j < 4; j++)
            #pragma unroll
            for (int r = 0; r < 4; r++) acc[i][j][r] = 0.f;

    const int nch = K >> 6;
    issue(0, 0); issue(1, 1);

    for (int it = 0; it < nch; it++) {
        if (it + 1 < nch) cpa_wait<1>(); else cpa_wait<0>();
        __syncthreads();
        if (it + 2 < nch) issue(it + 2, (it + 2) % 3);

        const int slot = it % 3;
        const uint32_t ab = smem_u + slot * AS_B;
        const uint32_t bb = smem_u + NSTG * AS_B + slot * BS_B;

        #pragma unroll
        for (int ks = 0; ks < 4; ks++) {
            unsigned a[4][4];
            #pragma unroll
            for (int mi = 0; mi < 4; mi++) {
                const int row = wm + mi * 16 + (lane & 15);
                const int ch = ks * 2 + (lane >> 4);
                ldsm_x4(a[mi], ab + row * 128 + ((ch ^ (row & 7)) << 4));
            }
            unsigned b[2][4];
            #pragma unroll
            for (int njp = 0; njp < 2; njp++) {
                const int krow = ks * 16 + (lane & 15);
                const int cn = (wn >> 3) + njp * 2 + (lane >> 4);
                ldsm_x4_t(b[njp], bb + krow * 256 + ((cn ^ (krow & 7)) << 4));
            }
            #pragma unroll
            for (int mi = 0; mi < 4; mi++)
                #pragma unroll
                for (int njp = 0; njp < 2; njp++) {
                    mma_h(acc[mi][njp * 2 + 0], a[mi], b[njp] + 0);
                    mma_h(acc[mi][njp * 2 + 1], a[mi], b[njp] + 2);
                }
        }
        // NOTE: no bottom __syncthreads — next iteration's top barrier
        // (after cpa_wait) orders these smem reads before slot reuse.
    }

    #pragma unroll
    for (int mi = 0; mi < 4; mi++) {
        #pragma unroll
        for (int half = 0; half < 2; half++) {
            const int r = m0 + wm + mi * 16 + grp + half * 8;
            if (r >= M) continue;
            #pragma unroll
            for (int nj = 0; nj < 4; nj++) {
                const int c = n0 + wn + nj * 8 + tig * 2;
                float2 v;
                v.x = acc[mi][nj][half * 2 + 0];
                v.y = acc[mi][nj][half * 2 + 1];
                if (bias) { v.x += bias[c]; v.y += bias[c + 1]; }
                if (mode == 2) {
                    Ch[(size_t)r * FFI + (c >> 1)] = __float2half_rn(v.x * gelu_tanh(v.y));
                } else if (mode == 1) {
                    unsigned u = pack2(v.x, v.y);
                    *reinterpret_cast<unsigned*>(Ch + (size_t)r * N + c) = u;
                } else {
                    if (res) {
                        const float2 rv =
                            *reinterpret_cast<const float2*>(res + (size_t)r * N + c);
                        v.x += rv.x; v.y += rv.y;
                    }
                    *reinterpret_cast<float2*>(Cf + (size_t)r * N + c) = v;
                }
            }
        }
    }
}

// ---------------------------------------------------------------------------
// fp16 flash attention: 4 warps, 128 q/CTA, 32 q/warp (2 m16 tiles), kt=64.
// K/V prefetch issued AFTER the top barrier -> single barrier per kt iter.
// smem: Qs/Ps 16KB @0 ; Ks 2x8KB @16384 ; Vs 2x8KB @32768  (total 48KB)
// ---------------------------------------------------------------------------
#define ATTN_SMEM 49152

__global__ __launch_bounds__(128, 2) void attn_h(
    const __half* __restrict__ Q, const __half* __restrict__ K,
    const __half* __restrict__ V, __half* __restrict__ O, int Sq, int Sk)
{
    extern __shared__ char smc[];
    const int tid = threadIdx.x, warp = tid >> 5, lane = tid & 31;
    const int grp = lane >> 2, tig = lane & 3;
    const int h = blockIdx.y, b = blockIdx.z;
    const int q0 = blockIdx.x * 128;
    const size_t qoff = (size_t)b * Sq * DIM + (size_t)h * DHEAD;
    const size_t koff = (size_t)b * Sk * DIM + (size_t)h * DHEAD;
    const int rbase = warp * 32;

    const uint32_t smem_u = (uint32_t)__cvta_generic_to_shared(smc);
    const uint32_t ks_u = smem_u + 16384;
    const uint32_t vs_u = smem_u + 32768;

    auto issue_kv = [&](int kt, int slot) {
        #pragma unroll
        for (int i = 0; i < 4; i++) {
            const int c = tid + i * 128;
            const int row = c >> 3, nc = c & 7;
            const int gr = kt * 64 + row;
            const bool ok = gr < Sk;
            const int grc = ok ? gr : 0;
            cpa16(ks_u + slot * 8192 + row * 128 + ((nc ^ (row & 7)) << 4),
                  K + koff + (size_t)grc * DIM + nc * 8, ok);
        }
        #pragma unroll
        for (int i = 0; i < 4; i++) {
            const int c = tid + i * 128;
            const int row = c >> 3, nc = c & 7;
            const int gr = kt * 64 + row;
            const bool ok = gr < Sk;
            const int grc = ok ? gr : 0;
            cpa16(vs_u + slot * 8192 + row * 128 + ((nc ^ (row & 7)) << 4),
                  V + koff + (size_t)grc * DIM + nc * 8, ok);
        }
        cpa_commit();
    };

    // Q tile load (scale pre-folded into wq)
    #pragma unroll
    for (int i = 0; i < 8; i++) {
        const int c = tid + i * 128;
        const int row = c >> 3, nc = c & 7;
        cpa16(smem_u + row * 128 + ((nc ^ (row & 7)) << 4),
              Q + qoff + (size_t)(q0 + row) * DIM + nc * 8, true);
    }
    cpa_commit();
    issue_kv(0, 0);

    unsigned qa[2][4][4];
    float o[2][8][4];
    #pragma unroll
    for (int t = 0; t < 2; t++)
        #pragma unroll
        for (int d = 0; d < 8; d++)
            #pragma unroll
            for (int r = 0; r < 4; r++) o[t][d][r] = 0.f;
    float mxA[2] = {-1e30f, -1e30f}, mxB[2] = {-1e30f, -1e30f};
    float lA[2] = {0.f, 0.f}, lB[2] = {0.f, 0.f};

    const int nkt = (Sk + 63) >> 6;
    for (int kt = 0; kt < nkt; kt++) {
        cpa_wait<0>();
        __syncthreads();
        if (kt + 1 < nkt) issue_kv(kt + 1, (kt + 1) & 1);

        if (kt == 0) {   // Q frags to registers (warp-private rows)
            #pragma unroll
            for (int t = 0; t < 2; t++)
                #pragma unroll
                for (int ks = 0; ks < 4; ks++) {
                    const int row = rbase + t * 16 + (lane & 15);
                    const int ch = ks * 2 + (lane >> 4);
                    ldsm_x4(qa[t][ks], smem_u + row * 128 + ((ch ^ (row & 7)) << 4));
                }
        }

        const uint32_t ksl = ks_u + (kt & 1) * 8192;
        const uint32_t vsl = vs_u + (kt & 1) * 8192;

        // ---- S = Q K^T ----
        float sc[2][8][4];
        #pragma unroll
        for (int t = 0; t < 2; t++)
            #pragma unroll
            for (int nj = 0; nj < 8; nj++)
                #pragma unroll
                for (int r = 0; r < 4; r++) sc[t][nj][r] = 0.f;

        #pragma unroll
        for (int ks = 0; ks < 4; ks++) {
            #pragma unroll
            for (int njp = 0; njp < 4; njp++) {
                unsigned kb[4];
                const int nrow = njp * 16 + (lane & 7) + (lane >> 4) * 8;
                const int kc = ks * 2 + ((lane >> 3) & 1);
                ldsm_x4(kb, ksl + nrow * 128 + ((kc ^ (nrow & 7)) << 4));
                #pragma unroll
                for (int t = 0; t < 2; t++) {
                    mma_h(sc[t][njp * 2 + 0], qa[t][ks], kb + 0);
                    mma_h(sc[t][njp * 2 + 1], qa[t][ks], kb + 2);
                }
            }
        }

        // mask padded keys
        if (kt * 64 + 64 > Sk) {
            #pragma unroll
            for (int t = 0; t < 2; t++)
                #pragma unroll
                for (int nj = 0; nj < 8; nj++) {
                    const int j = kt * 64 + nj * 8 + tig * 2;
                    if (j     >= Sk) { sc[t][nj][0] = -1e30f; sc[t][nj][2] = -1e30f; }
                    if (j + 1 >= Sk) { sc[t][nj][1] = -1e30f; sc[t][nj][3] = -1e30f; }
                }
        }

        // ---- online softmax ----
        #pragma unroll
        for (int t = 0; t < 2; t++) {
            float tm0 = -1e30f, tm1 = -1e30f;
            #pragma unroll
            for (int nj = 0; nj < 8; nj++) {
                tm0 = fmaxf(tm0, fmaxf(sc[t][nj][0], sc[t][nj][1]));
                tm1 = fmaxf(tm1, fmaxf(sc[t][nj][2], sc[t][nj][3]));
            }
            tm0 = fmaxf(tm0, __shfl_xor_sync(0xffffffffu, tm0, 1));
            tm0 = fmaxf(tm0, __shfl_xor_sync(0xffffffffu, tm0, 2));
            tm1 = fmaxf(tm1, __shfl_xor_sync(0xffffffffu, tm1, 1));
            tm1 = fmaxf(tm1, __shfl_xor_sync(0xffffffffu, tm1, 2));
            const float mn0 = fmaxf(mxA[t], tm0), mn1 = fmaxf(mxB[t], tm1);
            const float c0 = __expf(mxA[t] - mn0), c1 = __expf(mxB[t] - mn1);
            mxA[t] = mn0; mxB[t] = mn1;
            float s0 = 0.f, s1 = 0.f;
            #pragma unroll
            for (int nj = 0; nj < 8; nj++) {
                sc[t][nj][0] = __expf(sc[t][nj][0] - mn0);
                sc[t][nj][1] = __expf(sc[t][nj][1] - mn0);
                sc[t][nj][2] = __expf(sc[t][nj][2] - mn1);
                sc[t][nj][3] = __expf(sc[t][nj][3] - mn1);
                s0 += sc[t][nj][0] + sc[t][nj][1];
                s1 += sc[t][nj][2] + sc[t][nj][3];
            }
            s0 += __shfl_xor_sync(0xffffffffu, s0, 1);
            s0 += __shfl_xor_sync(0xffffffffu, s0, 2);
            s1 += __shfl_xor_sync(0xffffffffu, s1, 1);
            s1 += __shfl_xor_sync(0xffffffffu, s1, 2);
            lA[t] = lA[t] * c0 + s0;
            lB[t] = lB[t] * c1 + s1;
            #pragma unroll
            for (int d = 0; d < 8; d++) {
                o[t][d][0] *= c0; o[t][d][1] *= c0;
                o[t][d][2] *= c1; o[t][d][3] *= c1;
            }
        }

        // ---- publish P (half) to warp-private Ps rows (aliases Qs) ----
        #pragma unroll
        for (int t = 0; t < 2; t++)
            #pragma unroll
            for (int nj = 0; nj < 8; nj++) {
                const int r0 = rbase + t * 16 + grp;
                *reinterpret_cast<unsigned*>(smc + r0 * 128 +
                    ((nj ^ (r0 & 7)) << 4) + tig * 4) = pack2(sc[t][nj][0], sc[t][nj][1]);
                const int r1 = r0 + 8;
                *reinterpret_cast<unsigned*>(smc + r1 * 128 +
                    ((nj ^ (r1 & 7)) << 4) + tig * 4) = pack2(sc[t][nj][2], sc[t][nj][3]);
            }
        __syncwarp();

        // ---- O += P V ----
        #pragma unroll
        for (int kj = 0; kj < 4; kj++) {
            unsigned pa[2][4];
            #pragma unroll
            for (int t = 0; t < 2; t++) {
                const int row = rbase + t * 16 + (lane & 15);
                const int ch = kj * 2 + (lane >> 4);
                ldsm_x4(pa[t], smem_u + row * 128 + ((ch ^ (row & 7)) << 4));
            }
            #pragma unroll
            for (int dgp = 0; dgp < 4; dgp++) {
                unsigned vb[4];
                const int vrow = kj * 16 + (lane & 15);
                const int vc = dgp * 2 + (lane >> 4);
                ldsm_x4_t(vb, vsl + vrow * 128 + ((vc ^ (vrow & 7)) << 4));
                #pragma unroll
                for (int t = 0; t < 2; t++) {
                    mma_h(o[t][dgp * 2 + 0], pa[t], vb + 0);
                    mma_h(o[t][dgp * 2 + 1], pa[t], vb + 2);
                }
            }
        }
        // NOTE: no bottom __syncthreads — next iteration's top barrier
        // (after cpa_wait) orders K/V slot reads before prefetch reuse.
    }

    #pragma unroll
    for (int t = 0; t < 2; t++) {
        const float i0 = 1.f / lA[t], i1 = 1.f / lB[t];
        const int row0 = q0 + rbase + t * 16 + grp;
        #pragma unroll
        for (int d = 0; d < 8; d++) {
            *reinterpret_cast<unsigned*>(O + qoff + (size_t)row0 * DIM + d * 8 + tig * 2) =
                pack2(o[t][d][0] * i0, o[t][d][1] * i0);
            *reinterpret_cast<unsigned*>(O + qoff + (size_t)(row0 + 8) * DIM + d * 8 + tig * 2) =
                pack2(o[t][d][2] * i1, o[t][d][3] * i1);
        }
    }
}

// ---------------------------------------------------------------------------
extern "C" void kernel_launch(void* const* d_in, const int* in_sizes, int n_in,
                              void* d_out, int out_size)
{
    const float* hs   = (const float*)d_in[0];
    const float* ctx  = (const float*)d_in[1];
    const float* wq1  = (const float*)d_in[2];
    const float* wk1  = (const float*)d_in[3];
    const float* wv1  = (const float*)d_in[4];
    const float* wo1  = (const float*)d_in[5];
    const float* bo1  = (const float*)d_in[6];
    const float* wq2  = (const float*)d_in[7];
    const float* wk2  = (const float*)d_in[8];
    const float* wv2  = (const float*)d_in[9];
    const float* wo2  = (const float*)d_in[10];
    const float* bo2  = (const float*)d_in[11];
    const float* wff1 = (const float*)d_in[12];
    const float* bff1 = (const float*)d_in[13];
    const float* wff2 = (const float*)d_in[14];
    const float* bff2 = (const float*)d_in[15];
    const float* ln1g = (const float*)d_in[16];
    const float* ln1b = (const float*)d_in[17];
    const float* ln2g = (const float*)d_in[18];
    const float* ln2b = (const float*)d_in[19];
    const float* ln3g = (const float*)d_in[20];
    const float* ln3b = (const float*)d_in[21];
    float* out = (float*)d_out;

    __half *xn, *q, *k, *v, *ah, *gg, *wh;
    float *h, *bf1;
    cudaGetSymbolAddress((void**)&xn,  g_xnh);
    cudaGetSymbolAddress((void**)&q,   g_qh);
    cudaGetSymbolAddress((void**)&k,   g_kh);
    cudaGetSymbolAddress((void**)&v,   g_vh);
    cudaGetSymbolAddress((void**)&ah,  g_ah);
    cudaGetSymbolAddress((void**)&gg,  g_ggh);
    cudaGetSymbolAddress((void**)&wh,  g_wh);
    cudaGetSymbolAddress((void**)&h,   g_h);
    cudaGetSymbolAddress((void**)&bf1, g_bf1);

    cudaFuncSetAttribute(gemm_h, cudaFuncAttributeMaxDynamicSharedMemorySize, GEMM_SMEM);
    cudaFuncSetAttribute(attn_h, cudaFuncAttributeMaxDynamicSharedMemorySize, ATTN_SMEM);

    // ---- convert weights + context to fp16 (0.125 folded into wq) ----
    CJobs cj;
    const float* srcs[10] = {wq1, wk1, wv1, wo1, wq2, wk2, wv2, wo2, wff2, ctx};
    const int    offs[10] = {OWQ1, OWK1, OWV1, OWO1, OWQ2, OWK2, OWV2, OWO2, OWF2, OCTX};
    const int    lens[10] = {1048576, 1048576, 1048576, 1048576, 1048576, 786432, 786432,
                             1048576, 4194304, 236544};
    for (int i = 0; i < 10; i++) {
        cj.src[i] = srcs[i]; cj.dst[i] = wh + offs[i]; cj.n[i] = lens[i];
        cj.scale[i] = (i == 0 || i == 4) ? 0.125f : 1.0f;
    }
    conv_kernel<<<dim3(512, 10), 256>>>(cj);
    permute_ff1<<<dim3(16, 1024), 256>>>(wff1, wh + OWF1);
    permute_bias_ff1<<<dim3(16), 256>>>(bff1, bf1);

    const dim3 blk(256);
    const dim3 ablk(128);
    const dim3 g_attng(SEQ / 128, NHEADS, 4);

    GemmB gqkv{}, gwo1{}, gq2{}, gkv2{}, gwo2{}, gff1{}, gff2{};
    gqkv.W[0] = wh + OWQ1; gqkv.Ch[0] = q;
    gqkv.W[1] = wh + OWK1; gqkv.Ch[1] = k;
    gqkv.W[2] = wh + OWV1; gqkv.Ch[2] = v;
    gwo1.W[0] = wh + OWO1; gwo1.bias[0] = bo1; gwo1.res[0] = hs; gwo1.Cf[0] = h;
    gq2.W[0]  = wh + OWQ2; gq2.Ch[0]  = q;
    gkv2.W[0] = wh + OWK2; gkv2.Ch[0] = k;
    gkv2.W[1] = wh + OWV2; gkv2.Ch[1] = v;
    gwo2.W[0] = wh + OWO2; gwo2.bias[0] = bo2; gwo2.res[0] = h; gwo2.Cf[0] = h;
    gff1.W[0] = wh + OWF1; gff1.bias[0] = bf1; gff1.Ch[0] = gg;
    gff2.W[0] = wh + OWF2; gff2.bias[0] = bff2; gff2.res[0] = h; gff2.Cf[0] = out;

    // ---- self-attention ----
    ln_kernel<<<BROWS, blk>>>(hs, xn, ln1g, ln1b);
    gemm_h<<<dim3(8, 64, 3), blk, GEMM_SMEM>>>(xn, gqkv, BROWS, DIM, DIM, 1);
    attn_h<<<g_attng, ablk, ATTN_SMEM>>>(q, k, v, ah, SEQ, SEQ);
    gemm_h<<<dim3(8, 64, 1), blk, GEMM_SMEM>>>(ah, gwo1, BROWS, DIM, DIM, 0);

    // ---- cross-attention ----
    ln_kernel<<<BROWS, blk>>>(h, xn, ln2g, ln2b);
    gemm_h<<<dim3(8, 64, 1), blk, GEMM_SMEM>>>(xn, gq2, BROWS, DIM, DIM, 1);
    gemm_h<<<dim3(8, 3, 2), blk, GEMM_SMEM>>>(wh + OCTX, gkv2, CROWS, DIM, CTXD, 1);
    attn_h<<<g_attng, ablk, ATTN_SMEM>>>(q, k, v, ah, SEQ, TCTX);
    gemm_h<<<dim3(8, 64, 1), blk, GEMM_SMEM>>>(ah, gwo2, BROWS, DIM, DIM, 0);

    // ---- GEGLU feed-forward (fused into FF1 epilogue) ----
    ln_kernel<<<BROWS, blk>>>(h, xn, ln3g, ln3b);
    gemm_h<<<dim3(64, 64, 1), blk, GEMM_SMEM>>>(xn, gff1, BROWS, 2 * FFI, DIM, 2);
    gemm_h<<<dim3(8, 64, 1), blk, GEMM_SMEM>>>(gg, gff2, BROWS, DIM, FFI, 0);
}

// round 11
// speedup vs baseline: 1.1441x; 1.0186x over previous
#include <cuda_runtime.h>
#include <cuda_fp16.h>
#include <cstdint>
#include <cstddef>

// ---------------------------------------------------------------------------
#define BROWS   8192
#define CROWS   308
#define DIM     1024
#define CTXD    768
#define FFI     4096
#define SEQ     2048
#define TCTX    77
#define NHEADS  16
#define DHEAD   64

// ---------------------------------------------------------------------------
// Scratch
// ---------------------------------------------------------------------------
__device__ __half g_xnh[(size_t)BROWS * DIM];
__device__ __half g_qh [(size_t)BROWS * DIM];
__device__ __half g_kh [(size_t)BROWS * DIM];
__device__ __half g_vh [(size_t)BROWS * DIM];
__device__ __half g_ah [(size_t)BROWS * DIM];
__device__ __half g_ggh[(size_t)BROWS * FFI];
__device__ float  g_h  [(size_t)BROWS * DIM];

// half weights + context; wff1 column-interleaved (lin,gate)
#define OWQ1 0
#define OWK1 1048576
#define OWV1 2097152
#define OWO1 3145728
#define OWQ2 4194304
#define OWK2 5242880
#define OWV2 6029312
#define OWO2 6815744
#define OWF1 7864320
#define OWF2 16252928
#define OCTX 20447232
#define WHTOT 20683776
__device__ __half g_wh[WHTOT];
__device__ float  g_bf1[2 * FFI];   // permuted FF1 bias (fp32)

// ---------------------------------------------------------------------------
// helpers
// ---------------------------------------------------------------------------
__device__ __forceinline__ void mma_h(float c[4], const unsigned a[4], const unsigned b[2]) {
    asm volatile(
        "mma.sync.aligned.m16n8k16.row.col.f32.f16.f16.f32 "
        "{%0,%1,%2,%3}, {%4,%5,%6,%7}, {%8,%9}, {%0,%1,%2,%3};\n"
        : "+f"(c[0]), "+f"(c[1]), "+f"(c[2]), "+f"(c[3])
        : "r"(a[0]), "r"(a[1]), "r"(a[2]), "r"(a[3]), "r"(b[0]), "r"(b[1]));
}
__device__ __forceinline__ void ldsm_x4(unsigned r[4], uint32_t addr) {
    asm volatile("ldmatrix.sync.aligned.m8n8.x4.shared.b16 {%0,%1,%2,%3}, [%4];"
                 : "=r"(r[0]), "=r"(r[1]), "=r"(r[2]), "=r"(r[3]) : "r"(addr));
}
__device__ __forceinline__ void ldsm_x4_t(unsigned r[4], uint32_t addr) {
    asm volatile("ldmatrix.sync.aligned.m8n8.x4.trans.shared.b16 {%0,%1,%2,%3}, [%4];"
                 : "=r"(r[0]), "=r"(r[1]), "=r"(r[2]), "=r"(r[3]) : "r"(addr));
}
__device__ __forceinline__ void cpa16(uint32_t dst, const void* src, bool pred) {
    int sz = pred ? 16 : 0;
    asm volatile("cp.async.cg.shared.global [%0], [%1], 16, %2;\n"
                 :: "r"(dst), "l"(src), "r"(sz));
}
__device__ __forceinline__ void cpa_commit() { asm volatile("cp.async.commit_group;"); }
template<int N> __device__ __forceinline__ void cpa_wait() {
    asm volatile("cp.async.wait_group %0;" :: "n"(N));
}
__device__ __forceinline__ float gelu_tanh(float x) {
    const float x3 = x * x * x;
    return 0.5f * x * (1.f + tanhf(0.7978845608028654f * (x + 0.044715f * x3)));
}
__device__ __forceinline__ unsigned pack2(float a, float b) {
    __half2 h = __floats2half2_rn(a, b);
    return *reinterpret_cast<unsigned*>(&h);
}

// ---------------------------------------------------------------------------
// fp32 -> fp16 conversion pass (scale folds 0.125 into wq)
// ---------------------------------------------------------------------------
struct CJobs { const float* src[7]; __half* dst[7]; int n[7]; float scale[7]; };

__global__ __launch_bounds__(256) void conv_kernel(CJobs j) {
    const int job = blockIdx.y;
    const float* s = j.src[job];
    __half* d = j.dst[job];
    const int n = j.n[job];
    const float sc = j.scale[job];
    for (int i = (blockIdx.x * 256 + threadIdx.x) * 4; i < n; i += gridDim.x * 1024) {
        float4 v = *reinterpret_cast<const float4*>(s + i);
        uint2 u;
        u.x = pack2(v.x * sc, v.y * sc);
        u.y = pack2(v.z * sc, v.w * sc);
        *reinterpret_cast<uint2*>(d + i) = u;
    }
}

// Interleave wff1 columns: dst[k][2j]=lin col j, dst[k][2j+1]=gate col (j+FFI)
__global__ __launch_bounds__(256) void permute_ff1(
    const float* __restrict__ s, __half* __restrict__ d)
{
    const int k = blockIdx.y;
    const int j = blockIdx.x * 256 + threadIdx.x;
    const float lin = s[(size_t)k * (2 * FFI) + j];
    const float gt  = s[(size_t)k * (2 * FFI) + FFI + j];
    unsigned u = pack2(lin, gt);
    *reinterpret_cast<unsigned*>(d + (size_t)k * (2 * FFI) + 2 * j) = u;
}

__global__ __launch_bounds__(256) void permute_bias_ff1(
    const float* __restrict__ s, float* __restrict__ d)
{
    const int j = blockIdx.x * 256 + threadIdx.x;
    float2 v; v.x = s[j]; v.y = s[FFI + j];
    *reinterpret_cast<float2*>(d + 2 * j) = v;
}

// ---------------------------------------------------------------------------
// LayerNorm: fp32 in, fp16 out
// ---------------------------------------------------------------------------
__global__ __launch_bounds__(256) void ln_kernel(
    const float* __restrict__ x, __half* __restrict__ y,
    const float* __restrict__ gam, const float* __restrict__ bet)
{
    __shared__ float red[16];
    const int row = blockIdx.x;
    const int t = threadIdx.x;
    const float4 xv = reinterpret_cast<const float4*>(x + (size_t)row * DIM)[t];

    float s  = xv.x + xv.y + xv.z + xv.w;
    float sq = xv.x*xv.x + xv.y*xv.y + xv.z*xv.z + xv.w*xv.w;
    #pragma unroll
    for (int w = 16; w > 0; w >>= 1) {
        s  += __shfl_xor_sync(0xffffffffu, s,  w);
        sq += __shfl_xor_sync(0xffffffffu, sq, w);
    }
    const int wid = t >> 5, lid = t & 31;
    if (lid == 0) { red[wid] = s; red[8 + wid] = sq; }
    __syncthreads();
    if (t < 32) {
        float a  = (lid < 8) ? red[lid]     : 0.f;
        float aq = (lid < 8) ? red[8 + lid] : 0.f;
        #pragma unroll
        for (int w = 4; w > 0; w >>= 1) {
            a  += __shfl_xor_sync(0xffffffffu, a,  w);
            aq += __shfl_xor_sync(0xffffffffu, aq, w);
        }
        if (lid == 0) { red[0] = a; red[8] = aq; }
    }
    __syncthreads();
    const float mean = red[0] * (1.f / DIM);
    const float var  = red[8] * (1.f / DIM) - mean * mean;
    const float inv  = rsqrtf(var + 1e-5f);

    const float4 gv = reinterpret_cast<const float4*>(gam)[t];
    const float4 bv = reinterpret_cast<const float4*>(bet)[t];
    uint2 u;
    u.x = pack2((xv.x - mean) * inv * gv.x + bv.x, (xv.y - mean) * inv * gv.y + bv.y);
    u.y = pack2((xv.z - mean) * inv * gv.z + bv.z, (xv.w - mean) * inv * gv.w + bv.w);
    *reinterpret_cast<uint2*>(y + (size_t)row * DIM + t * 4) = u;
}

// ---------------------------------------------------------------------------
// fp16 GEMM (R7 config): 128x128 CTA, 8 warps (2x4), warp tile 64x32,
// k-chunk 64, 3-stage cp.async, occ 2. ONE barrier per k-iteration.
// mode: 0 = fp32 store, 1 = fp16 store, 2 = GEGLU pairs -> Ch FFI-wide
// ---------------------------------------------------------------------------
struct GemmB {
    const __half* W[3];
    const float* bias[3];
    const float* res[3];
    float* Cf[3];
    __half* Ch[3];
};

#define NSTG 3
#define AS_B 16384                 // A stage bytes (128 rows * 128B)
#define BS_B 16384                 // B stage bytes (64 rows * 256B)
#define GEMM_SMEM (NSTG * (AS_B + BS_B))   // 98304

__global__ __launch_bounds__(256, 2) void gemm_h(
    const __half* __restrict__ A, GemmB gb, int M, int N, int K, int mode)
{
    extern __shared__ char smc[];
    const int z = blockIdx.z;
    const __half* W   = gb.W[z];
    const float* bias = gb.bias[z];
    const float* res  = gb.res[z];
    float* Cf         = gb.Cf[z];
    __half* Ch        = gb.Ch[z];

    const int tid = threadIdx.x, warp = tid >> 5, lane = tid & 31;
    const int grp = lane >> 2, tig = lane & 3;
    const int wm = (warp & 1) * 64, wn = (warp >> 1) * 32;
    const int m0 = blockIdx.y << 7, n0 = blockIdx.x << 7;

    const uint32_t smem_u = (uint32_t)__cvta_generic_to_shared(smc);

    auto issue = [&](int ch, int slot) {
        const int k0 = ch << 6;
        const uint32_t ab = smem_u + slot * AS_B;
        #pragma unroll
        for (int i = 0; i < 4; i++) {
            const int idx = tid + i * 256;
            const int row = idx >> 3, c = idx & 7;
            int gr = m0 + row; if (gr >= M) gr = M - 1;
            cpa16(ab + row * 128 + ((c ^ (row & 7)) << 4),
                  A + (size_t)gr * K + k0 + c * 8, true);
        }
        const uint32_t bb = smem_u + NSTG * AS_B + slot * BS_B;
        #pragma unroll
        for (int i = 0; i < 4; i++) {
            const int idx = tid + i * 256;
            const int row = idx >> 4, c = idx & 15;
            cpa16(bb + row * 256 + ((c ^ (row & 7)) << 4),
                  W + (size_t)(k0 + row) * N + n0 + c * 8, true);
        }
        cpa_commit();
    };

    float acc[4][4][4];
    #pragma unroll
    for (int i = 0; i < 4; i++)
        #pragma unroll
        for (int j = 0; j < 4; j++)
            #pragma unroll
            for (int r = 0; r < 4; r++) acc[i][j][r] = 0.f;

    const int nch = K >> 6;
    issue(0, 0); issue(1, 1);

    for (int it = 0; it < nch; it++) {
        if (it + 1 < nch) cpa_wait<1>(); else cpa_wait<0>();
        __syncthreads();
        if (it + 2 < nch) issue(it + 2, (it + 2) % 3);

        const int slot = it % 3;
        const uint32_t ab = smem_u + slot * AS_B;
        const uint32_t bb = smem_u + NSTG * AS_B + slot * BS_B;

        #pragma unroll
        for (int ks = 0; ks < 4; ks++) {
            unsigned a[4][4];
            #pragma unroll
            for (int mi = 0; mi < 4; mi++) {
                const int row = wm + mi * 16 + (lane & 15);
                const int ch = ks * 2 + (lane >> 4);
                ldsm_x4(a[mi], ab + row * 128 + ((ch ^ (row & 7)) << 4));
            }
            unsigned b[2][4];
            #pragma unroll
            for (int njp = 0; njp < 2; njp++) {
                const int krow = ks * 16 + (lane & 15);
                const int cn = (wn >> 3) + njp * 2 + (lane >> 4);
                ldsm_x4_t(b[njp], bb + krow * 256 + ((cn ^ (krow & 7)) << 4));
            }
            #pragma unroll
            for (int mi = 0; mi < 4; mi++)
                #pragma unroll
                for (int njp = 0; njp < 2; njp++) {
                    mma_h(acc[mi][njp * 2 + 0], a[mi], b[njp] + 0);
                    mma_h(acc[mi][njp * 2 + 1], a[mi], b[njp] + 2);
                }
        }
        // no bottom __syncthreads — next iteration's top barrier suffices.
    }

    #pragma unroll
    for (int mi = 0; mi < 4; mi++) {
        #pragma unroll
        for (int half = 0; half < 2; half++) {
            const int r = m0 + wm + mi * 16 + grp + half * 8;
            if (r >= M) continue;
            #pragma unroll
            for (int nj = 0; nj < 4; nj++) {
                const int c = n0 + wn + nj * 8 + tig * 2;
                float2 v;
                v.x = acc[mi][nj][half * 2 + 0];
                v.y = acc[mi][nj][half * 2 + 1];
                if (bias) { v.x += bias[c]; v.y += bias[c + 1]; }
                if (mode == 2) {
                    Ch[(size_t)r * FFI + (c >> 1)] = __float2half_rn(v.x * gelu_tanh(v.y));
                } else if (mode == 1) {
                    unsigned u = pack2(v.x, v.y);
                    *reinterpret_cast<unsigned*>(Ch + (size_t)r * N + c) = u;
                } else {
                    if (res) {
                        const float2 rv =
                            *reinterpret_cast<const float2*>(res + (size_t)r * N + c);
                        v.x += rv.x; v.y += rv.y;
                    }
                    *reinterpret_cast<float2*>(Cf + (size_t)r * N + c) = v;
                }
            }
        }
    }
}

// ---------------------------------------------------------------------------
// fp16 flash attention: 4 warps, 128 q/CTA, 32 q/warp (2 m16 tiles), kt=64.
// Single barrier per kt iteration. smem 48KB.
// ---------------------------------------------------------------------------
#define ATTN_SMEM 49152

__global__ __launch_bounds__(128, 2) void attn_h(
    const __half* __restrict__ Q, const __half* __restrict__ K,
    const __half* __restrict__ V, __half* __restrict__ O, int Sq, int Sk)
{
    extern __shared__ char smc[];
    const int tid = threadIdx.x, warp = tid >> 5, lane = tid & 31;
    const int grp = lane >> 2, tig = lane & 3;
    const int h = blockIdx.y, b = blockIdx.z;
    const int q0 = blockIdx.x * 128;
    const size_t qoff = (size_t)b * Sq * DIM + (size_t)h * DHEAD;
    const size_t koff = (size_t)b * Sk * DIM + (size_t)h * DHEAD;
    const int rbase = warp * 32;

    const uint32_t smem_u = (uint32_t)__cvta_generic_to_shared(smc);
    const uint32_t ks_u = smem_u + 16384;
    const uint32_t vs_u = smem_u + 32768;

    auto issue_kv = [&](int kt, int slot) {
        #pragma unroll
        for (int i = 0; i < 4; i++) {
            const int c = tid + i * 128;
            const int row = c >> 3, nc = c & 7;
            const int gr = kt * 64 + row;
            const bool ok = gr < Sk;
            const int grc = ok ? gr : 0;
            cpa16(ks_u + slot * 8192 + row * 128 + ((nc ^ (row & 7)) << 4),
                  K + koff + (size_t)grc * DIM + nc * 8, ok);
        }
        #pragma unroll
        for (int i = 0; i < 4; i++) {
            const int c = tid + i * 128;
            const int row = c >> 3, nc = c & 7;
            const int gr = kt * 64 + row;
            const bool ok = gr < Sk;
            const int grc = ok ? gr : 0;
            cpa16(vs_u + slot * 8192 + row * 128 + ((nc ^ (row & 7)) << 4),
                  V + koff + (size_t)grc * DIM + nc * 8, ok);
        }
        cpa_commit();
    };

    #pragma unroll
    for (int i = 0; i < 8; i++) {
        const int c = tid + i * 128;
        const int row = c >> 3, nc = c & 7;
        cpa16(smem_u + row * 128 + ((nc ^ (row & 7)) << 4),
              Q + qoff + (size_t)(q0 + row) * DIM + nc * 8, true);
    }
    cpa_commit();
    issue_kv(0, 0);

    unsigned qa[2][4][4];
    float o[2][8][4];
    #pragma unroll
    for (int t = 0; t < 2; t++)
        #pragma unroll
        for (int d = 0; d < 8; d++)
            #pragma unroll
            for (int r = 0; r < 4; r++) o[t][d][r] = 0.f;
    float mxA[2] = {-1e30f, -1e30f}, mxB[2] = {-1e30f, -1e30f};
    float lA[2] = {0.f, 0.f}, lB[2] = {0.f, 0.f};

    const int nkt = (Sk + 63) >> 6;
    for (int kt = 0; kt < nkt; kt++) {
        cpa_wait<0>();
        __syncthreads();
        if (kt + 1 < nkt) issue_kv(kt + 1, (kt + 1) & 1);

        if (kt == 0) {
            #pragma unroll
            for (int t = 0; t < 2; t++)
                #pragma unroll
                for (int ks = 0; ks < 4; ks++) {
                    const int row = rbase + t * 16 + (lane & 15);
                    const int ch = ks * 2 + (lane >> 4);
                    ldsm_x4(qa[t][ks], smem_u + row * 128 + ((ch ^ (row & 7)) << 4));
                }
        }

        const uint32_t ksl = ks_u + (kt & 1) * 8192;
        const uint32_t vsl = vs_u + (kt & 1) * 8192;

        float sc[2][8][4];
        #pragma unroll
        for (int t = 0; t < 2; t++)
            #pragma unroll
            for (int nj = 0; nj < 8; nj++)
                #pragma unroll
                for (int r = 0; r < 4; r++) sc[t][nj][r] = 0.f;

        #pragma unroll
        for (int ks = 0; ks < 4; ks++) {
            #pragma unroll
            for (int njp = 0; njp < 4; njp++) {
                unsigned kb[4];
                const int nrow = njp * 16 + (lane & 7) + (lane >> 4) * 8;
                const int kc = ks * 2 + ((lane >> 3) & 1);
                ldsm_x4(kb, ksl + nrow * 128 + ((kc ^ (nrow & 7)) << 4));
                #pragma unroll
                for (int t = 0; t < 2; t++) {
                    mma_h(sc[t][njp * 2 + 0], qa[t][ks], kb + 0);
                    mma_h(sc[t][njp * 2 + 1], qa[t][ks], kb + 2);
                }
            }
        }

        if (kt * 64 + 64 > Sk) {
            #pragma unroll
            for (int t = 0; t < 2; t++)
                #pragma unroll
                for (int nj = 0; nj < 8; nj++) {
                    const int j = kt * 64 + nj * 8 + tig * 2;
                    if (j     >= Sk) { sc[t][nj][0] = -1e30f; sc[t][nj][2] = -1e30f; }
                    if (j + 1 >= Sk) { sc[t][nj][1] = -1e30f; sc[t][nj][3] = -1e30f; }
                }
        }

        #pragma unroll
        for (int t = 0; t < 2; t++) {
            float tm0 = -1e30f, tm1 = -1e30f;
            #pragma unroll
            for (int nj = 0; nj < 8; nj++) {
                tm0 = fmaxf(tm0, fmaxf(sc[t][nj][0], sc[t][nj][1]));
                tm1 = fmaxf(tm1, fmaxf(sc[t][nj][2], sc[t][nj][3]));
            }
            tm0 = fmaxf(tm0, __shfl_xor_sync(0xffffffffu, tm0, 1));
            tm0 = fmaxf(tm0, __shfl_xor_sync(0xffffffffu, tm0, 2));
            tm1 = fmaxf(tm1, __shfl_xor_sync(0xffffffffu, tm1, 1));
            tm1 = fmaxf(tm1, __shfl_xor_sync(0xffffffffu, tm1, 2));
            const float mn0 = fmaxf(mxA[t], tm0), mn1 = fmaxf(mxB[t], tm1);
            const float c0 = __expf(mxA[t] - mn0), c1 = __expf(mxB[t] - mn1);
            mxA[t] = mn0; mxB[t] = mn1;
            float s0 = 0.f, s1 = 0.f;
            #pragma unroll
            for (int nj = 0; nj < 8; nj++) {
                sc[t][nj][0] = __expf(sc[t][nj][0] - mn0);
                sc[t][nj][1] = __expf(sc[t][nj][1] - mn0);
                sc[t][nj][2] = __expf(sc[t][nj][2] - mn1);
                sc[t][nj][3] = __expf(sc[t][nj][3] - mn1);
                s0 += sc[t][nj][0] + sc[t][nj][1];
                s1 += sc[t][nj][2] + sc[t][nj][3];
            }
            s0 += __shfl_xor_sync(0xffffffffu, s0, 1);
            s0 += __shfl_xor_sync(0xffffffffu, s0, 2);
            s1 += __shfl_xor_sync(0xffffffffu, s1, 1);
            s1 += __shfl_xor_sync(0xffffffffu, s1, 2);
            lA[t] = lA[t] * c0 + s0;
            lB[t] = lB[t] * c1 + s1;
            #pragma unroll
            for (int d = 0; d < 8; d++) {
                o[t][d][0] *= c0; o[t][d][1] *= c0;
                o[t][d][2] *= c1; o[t][d][3] *= c1;
            }
        }

        #pragma unroll
        for (int t = 0; t < 2; t++)
            #pragma unroll
            for (int nj = 0; nj < 8; nj++) {
                const int r0 = rbase + t * 16 + grp;
                *reinterpret_cast<unsigned*>(smc + r0 * 128 +
                    ((nj ^ (r0 & 7)) << 4) + tig * 4) = pack2(sc[t][nj][0], sc[t][nj][1]);
                const int r1 = r0 + 8;
                *reinterpret_cast<unsigned*>(smc + r1 * 128 +
                    ((nj ^ (r1 & 7)) << 4) + tig * 4) = pack2(sc[t][nj][2], sc[t][nj][3]);
            }
        __syncwarp();

        #pragma unroll
        for (int kj = 0; kj < 4; kj++) {
            unsigned pa[2][4];
            #pragma unroll
            for (int t = 0; t < 2; t++) {
                const int row = rbase + t * 16 + (lane & 15);
                const int ch = kj * 2 + (lane >> 4);
                ldsm_x4(pa[t], smem_u + row * 128 + ((ch ^ (row & 7)) << 4));
            }
            #pragma unroll
            for (int dgp = 0; dgp < 4; dgp++) {
                unsigned vb[4];
                const int vrow = kj * 16 + (lane & 15);
                const int vc = dgp * 2 + (lane >> 4);
                ldsm_x4_t(vb, vsl + vrow * 128 + ((vc ^ (vrow & 7)) << 4));
                #pragma unroll
                for (int t = 0; t < 2; t++) {
                    mma_h(o[t][dgp * 2 + 0], pa[t], vb + 0);
                    mma_h(o[t][dgp * 2 + 1], pa[t], vb + 2);
                }
            }
        }
    }

    #pragma unroll
    for (int t = 0; t < 2; t++) {
        const float i0 = 1.f / lA[t], i1 = 1.f / lB[t];
        const int row0 = q0 + rbase + t * 16 + grp;
        #pragma unroll
        for (int d = 0; d < 8; d++) {
            *reinterpret_cast<unsigned*>(O + qoff + (size_t)row0 * DIM + d * 8 + tig * 2) =
                pack2(o[t][d][0] * i0, o[t][d][1] * i0);
            *reinterpret_cast<unsigned*>(O + qoff + (size_t)(row0 + 8) * DIM + d * 8 + tig * 2) =
                pack2(o[t][d][2] * i1, o[t][d][3] * i1);
        }
    }
}

// ---------------------------------------------------------------------------
extern "C" void kernel_launch(void* const* d_in, const int* in_sizes, int n_in,
                              void* d_out, int out_size)
{
    const float* hs   = (const float*)d_in[0];
    const float* ctx  = (const float*)d_in[1];
    const float* wq1  = (const float*)d_in[2];
    const float* wk1  = (const float*)d_in[3];
    const float* wv1  = (const float*)d_in[4];
    const float* wo1  = (const float*)d_in[5];
    const float* bo1  = (const float*)d_in[6];
    const float* wq2  = (const float*)d_in[7];
    const float* wk2  = (const float*)d_in[8];
    const float* wv2  = (const float*)d_in[9];
    const float* wo2  = (const float*)d_in[10];
    const float* bo2  = (const float*)d_in[11];
    const float* wff1 = (const float*)d_in[12];
    const float* bff1 = (const float*)d_in[13];
    const float* wff2 = (const float*)d_in[14];
    const float* bff2 = (const float*)d_in[15];
    const float* ln1g = (const float*)d_in[16];
    const float* ln1b = (const float*)d_in[17];
    const float* ln2g = (const float*)d_in[18];
    const float* ln2b = (const float*)d_in[19];
    const float* ln3g = (const float*)d_in[20];
    const float* ln3b = (const float*)d_in[21];
    float* out = (float*)d_out;

    __half *xn, *q, *k, *v, *ah, *gg, *wh;
    float *h, *bf1;
    cudaGetSymbolAddress((void**)&xn,  g_xnh);
    cudaGetSymbolAddress((void**)&q,   g_qh);
    cudaGetSymbolAddress((void**)&k,   g_kh);
    cudaGetSymbolAddress((void**)&v,   g_vh);
    cudaGetSymbolAddress((void**)&ah,  g_ah);
    cudaGetSymbolAddress((void**)&gg,  g_ggh);
    cudaGetSymbolAddress((void**)&wh,  g_wh);
    cudaGetSymbolAddress((void**)&h,   g_h);
    cudaGetSymbolAddress((void**)&bf1, g_bf1);

    // one-time infra (streams/events are host resources, not device allocs)
    static bool init_done = false;
    static cudaStream_t s2;
    static cudaEvent_t evRoot, evE, evL, evAT, evKV;
    if (!init_done) {
        cudaFuncSetAttribute(gemm_h, cudaFuncAttributeMaxDynamicSharedMemorySize, GEMM_SMEM);
        cudaFuncSetAttribute(attn_h, cudaFuncAttributeMaxDynamicSharedMemorySize, ATTN_SMEM);
        cudaStreamCreateWithFlags(&s2, cudaStreamNonBlocking);
        cudaEventCreateWithFlags(&evRoot, cudaEventDisableTiming);
        cudaEventCreateWithFlags(&evE,    cudaEventDisableTiming);
        cudaEventCreateWithFlags(&evL,    cudaEventDisableTiming);
        cudaEventCreateWithFlags(&evAT,   cudaEventDisableTiming);
        cudaEventCreateWithFlags(&evKV,   cudaEventDisableTiming);
        init_done = true;
    }

    // ---- weight-conversion job tables ----
    // early: only what the QKV GEMM needs
    CJobs cjE;
    {
        const float* s[3] = {wq1, wk1, wv1};
        const int    o[3] = {OWQ1, OWK1, OWV1};
        for (int i = 0; i < 3; i++) {
            cjE.src[i] = s[i]; cjE.dst[i] = wh + o[i]; cjE.n[i] = 1048576;
            cjE.scale[i] = (i == 0) ? 0.125f : 1.0f;
        }
    }
    // late: everything else (consumed from WO1 onward / by kv2)
    CJobs cjL;
    {
        const float* s[7] = {wo1, wq2, wk2, wv2, wo2, wff2, ctx};
        const int    o[7] = {OWO1, OWQ2, OWK2, OWV2, OWO2, OWF2, OCTX};
        const int    n[7] = {1048576, 1048576, 786432, 786432, 1048576, 4194304, 236544};
        for (int i = 0; i < 7; i++) {
            cjL.src[i] = s[i]; cjL.dst[i] = wh + o[i]; cjL.n[i] = n[i];
            cjL.scale[i] = (i == 1) ? 0.125f : 1.0f;
        }
    }

    const dim3 blk(256);
    const dim3 ablk(128);
    const dim3 g_attng(SEQ / 128, NHEADS, 4);

    GemmB gqkv{}, gwo1{}, gq2{}, gkv2{}, gwo2{}, gff1{}, gff2{};
    gqkv.W[0] = wh + OWQ1; gqkv.Ch[0] = q;
    gqkv.W[1] = wh + OWK1; gqkv.Ch[1] = k;
    gqkv.W[2] = wh + OWV1; gqkv.Ch[2] = v;
    gwo1.W[0] = wh + OWO1; gwo1.bias[0] = bo1; gwo1.res[0] = hs; gwo1.Cf[0] = h;
    gq2.W[0]  = wh + OWQ2; gq2.Ch[0]  = q;
    gkv2.W[0] = wh + OWK2; gkv2.Ch[0] = k;
    gkv2.W[1] = wh + OWV2; gkv2.Ch[1] = v;
    gwo2.W[0] = wh + OWO2; gwo2.bias[0] = bo2; gwo2.res[0] = h; gwo2.Cf[0] = h;
    gff1.W[0] = wh + OWF1; gff1.bias[0] = bf1; gff1.Ch[0] = gg;
    gff2.W[0] = wh + OWF2; gff2.bias[0] = bff2; gff2.res[0] = h; gff2.Cf[0] = out;

    // ---- fork stream 2 into the (captured) main stream's graph ----
    cudaEventRecord(evRoot, 0);
    cudaStreamWaitEvent(s2, evRoot, 0);

    // s2: early conversion (QKV weights), then the late bulk + FF1 permutes
    conv_kernel<<<dim3(256, 3), blk, 0, s2>>>(cjE);
    cudaEventRecord(evE, s2);
    conv_kernel<<<dim3(512, 7), blk, 0, s2>>>(cjL);
    permute_ff1<<<dim3(16, 1024), blk, 0, s2>>>(wff1, wh + OWF1);
    permute_bias_ff1<<<dim3(16), blk, 0, s2>>>(bff1, bf1);
    cudaEventRecord(evL, s2);

    // ---- main: self-attention block (overlaps late conversion) ----
    ln_kernel<<<BROWS, blk>>>(hs, xn, ln1g, ln1b);
    cudaStreamWaitEvent(0, evE, 0);
    gemm_h<<<dim3(8, 64, 3), blk, GEMM_SMEM>>>(xn, gqkv, BROWS, DIM, DIM, 1);
    attn_h<<<g_attng, ablk, ATTN_SMEM>>>(q, k, v, ah, SEQ, SEQ);
    cudaEventRecord(evAT, 0);

    // s2: kv2 GEMM (needs late conv + self-attn done w/ k,v buffers)
    cudaStreamWaitEvent(s2, evAT, 0);
    gemm_h<<<dim3(8, 3, 2), blk, GEMM_SMEM, s2>>>(wh + OCTX, gkv2, CROWS, DIM, CTXD, 1);
    cudaEventRecord(evKV, s2);

    // main: WO1 + cross-attention chain (kv2 overlaps WO1/ln2/q2)
    cudaStreamWaitEvent(0, evL, 0);
    gemm_h<<<dim3(8, 64, 1), blk, GEMM_SMEM>>>(ah, gwo1, BROWS, DIM, DIM, 0);
    ln_kernel<<<BROWS, blk>>>(h, xn, ln2g, ln2b);
    gemm_h<<<dim3(8, 64, 1), blk, GEMM_SMEM>>>(xn, gq2, BROWS, DIM, DIM, 1);
    cudaStreamWaitEvent(0, evKV, 0);
    attn_h<<<g_attng, ablk, ATTN_SMEM>>>(q, k, v, ah, SEQ, TCTX);
    gemm_h<<<dim3(8, 64, 1), blk, GEMM_SMEM>>>(ah, gwo2, BROWS, DIM, DIM, 0);

    // ---- GEGLU feed-forward (fused into FF1 epilogue) ----
    ln_kernel<<<BROWS, blk>>>(h, xn, ln3g, ln3b);
    gemm_h<<<dim3(64, 64, 1), blk, GEMM_SMEM>>>(xn, gff1, BROWS, 2 * FFI, DIM, 2);
    gemm_h<<<dim3(8, 64, 1), blk, GEMM_SMEM>>>(gg, gff2, BROWS, DIM, FFI, 0);
}

// round 12
// speedup vs baseline: 1.1633x; 1.0168x over previous
#include <cuda_runtime.h>
#include <cuda_fp16.h>
#include <cstdint>
#include <cstddef>

// ---------------------------------------------------------------------------
#define BROWS   8192
#define CROWS   308
#define DIM     1024
#define CTXD    768
#define FFI     4096
#define SEQ     2048
#define TCTX    77
#define NHEADS  16
#define DHEAD   64

// ---------------------------------------------------------------------------
// Scratch
// ---------------------------------------------------------------------------
__device__ __half g_xnh[(size_t)BROWS * DIM];
__device__ __half g_qh [(size_t)BROWS * DIM];
__device__ __half g_kh [(size_t)BROWS * DIM];
__device__ __half g_vh [(size_t)BROWS * DIM];
__device__ __half g_ah [(size_t)BROWS * DIM];
__device__ __half g_ggh[(size_t)BROWS * FFI];
__device__ float  g_h  [(size_t)BROWS * DIM];

// half weights + context; wff1 column-interleaved (lin,gate)
#define OWQ1 0
#define OWK1 1048576
#define OWV1 2097152
#define OWO1 3145728
#define OWQ2 4194304
#define OWK2 5242880
#define OWV2 6029312
#define OWO2 6815744
#define OWF1 7864320
#define OWF2 16252928
#define OCTX 20447232
#define WHTOT 20683776
__device__ __half g_wh[WHTOT];
__device__ float  g_bf1[2 * FFI];   // permuted FF1 bias (fp32)

// ---------------------------------------------------------------------------
// helpers
// ---------------------------------------------------------------------------
__device__ __forceinline__ void mma_h(float c[4], const unsigned a[4], const unsigned b[2]) {
    asm volatile(
        "mma.sync.aligned.m16n8k16.row.col.f32.f16.f16.f32 "
        "{%0,%1,%2,%3}, {%4,%5,%6,%7}, {%8,%9}, {%0,%1,%2,%3};\n"
        : "+f"(c[0]), "+f"(c[1]), "+f"(c[2]), "+f"(c[3])
        : "r"(a[0]), "r"(a[1]), "r"(a[2]), "r"(a[3]), "r"(b[0]), "r"(b[1]));
}
__device__ __forceinline__ void ldsm_x4(unsigned r[4], uint32_t addr) {
    asm volatile("ldmatrix.sync.aligned.m8n8.x4.shared.b16 {%0,%1,%2,%3}, [%4];"
                 : "=r"(r[0]), "=r"(r[1]), "=r"(r[2]), "=r"(r[3]) : "r"(addr));
}
__device__ __forceinline__ void ldsm_x4_t(unsigned r[4], uint32_t addr) {
    asm volatile("ldmatrix.sync.aligned.m8n8.x4.trans.shared.b16 {%0,%1,%2,%3}, [%4];"
                 : "=r"(r[0]), "=r"(r[1]), "=r"(r[2]), "=r"(r[3]) : "r"(addr));
}
__device__ __forceinline__ void cpa16(uint32_t dst, const void* src, bool pred) {
    int sz = pred ? 16 : 0;
    asm volatile("cp.async.cg.shared.global [%0], [%1], 16, %2;\n"
                 :: "r"(dst), "l"(src), "r"(sz));
}
__device__ __forceinline__ void cpa_commit() { asm volatile("cp.async.commit_group;"); }
template<int N> __device__ __forceinline__ void cpa_wait() {
    asm volatile("cp.async.wait_group %0;" :: "n"(N));
}
__device__ __forceinline__ float gelu_tanh(float x) {
    const float x3 = x * x * x;
    return 0.5f * x * (1.f + tanhf(0.7978845608028654f * (x + 0.044715f * x3)));
}
__device__ __forceinline__ unsigned pack2(float a, float b) {
    __half2 h = __floats2half2_rn(a, b);
    return *reinterpret_cast<unsigned*>(&h);
}

// ---------------------------------------------------------------------------
// fp32 -> fp16 conversion pass (scale folds 0.125 into wq)
// ---------------------------------------------------------------------------
struct CJobs { const float* src[7]; __half* dst[7]; int n[7]; float scale[7]; };

__global__ __launch_bounds__(256) void conv_kernel(CJobs j) {
    const int job = blockIdx.y;
    const float* s = j.src[job];
    __half* d = j.dst[job];
    const int n = j.n[job];
    const float sc = j.scale[job];
    for (int i = (blockIdx.x * 256 + threadIdx.x) * 4; i < n; i += gridDim.x * 1024) {
        float4 v = *reinterpret_cast<const float4*>(s + i);
        uint2 u;
        u.x = pack2(v.x * sc, v.y * sc);
        u.y = pack2(v.z * sc, v.w * sc);
        *reinterpret_cast<uint2*>(d + i) = u;
    }
}

// Interleave wff1 columns: dst[k][2j]=lin col j, dst[k][2j+1]=gate col (j+FFI)
__global__ __launch_bounds__(256) void permute_ff1(
    const float* __restrict__ s, __half* __restrict__ d)
{
    const int k = blockIdx.y;
    const int j = blockIdx.x * 256 + threadIdx.x;
    const float lin = s[(size_t)k * (2 * FFI) + j];
    const float gt  = s[(size_t)k * (2 * FFI) + FFI + j];
    unsigned u = pack2(lin, gt);
    *reinterpret_cast<unsigned*>(d + (size_t)k * (2 * FFI) + 2 * j) = u;
}

__global__ __launch_bounds__(256) void permute_bias_ff1(
    const float* __restrict__ s, float* __restrict__ d)
{
    const int j = blockIdx.x * 256 + threadIdx.x;
    float2 v; v.x = s[j]; v.y = s[FFI + j];
    *reinterpret_cast<float2*>(d + 2 * j) = v;
}

// ---------------------------------------------------------------------------
// LayerNorm v2: 2 rows per block, 128 threads/row (8 elems/thread).
// fp32 in, fp16 out.
// ---------------------------------------------------------------------------
__global__ __launch_bounds__(256) void ln_kernel(
    const float* __restrict__ x, __half* __restrict__ y,
    const float* __restrict__ gam, const float* __restrict__ bet)
{
    __shared__ float red[2][10];
    const int half = threadIdx.x >> 7;        // 0/1 -> row within block
    const int lt   = threadIdx.x & 127;       // 0..127
    const int row  = blockIdx.x * 2 + half;
    const int wid  = lt >> 5, lid = lt & 31;

    const float4 xv0 = reinterpret_cast<const float4*>(x + (size_t)row * DIM)[lt * 2];
    const float4 xv1 = reinterpret_cast<const float4*>(x + (size_t)row * DIM)[lt * 2 + 1];

    float s  = xv0.x + xv0.y + xv0.z + xv0.w + xv1.x + xv1.y + xv1.z + xv1.w;
    float sq = xv0.x*xv0.x + xv0.y*xv0.y + xv0.z*xv0.z + xv0.w*xv0.w
             + xv1.x*xv1.x + xv1.y*xv1.y + xv1.z*xv1.z + xv1.w*xv1.w;
    #pragma unroll
    for (int w = 16; w > 0; w >>= 1) {
        s  += __shfl_xor_sync(0xffffffffu, s,  w);
        sq += __shfl_xor_sync(0xffffffffu, sq, w);
    }
    if (lid == 0) { red[half][wid] = s; red[half][4 + wid] = sq; }
    __syncthreads();
    if (lt < 32) {
        float a  = (lid < 4) ? red[half][lid]     : 0.f;
        float aq = (lid < 4) ? red[half][4 + lid] : 0.f;
        #pragma unroll
        for (int w = 2; w > 0; w >>= 1) {
            a  += __shfl_xor_sync(0xffffffffu, a,  w);
            aq += __shfl_xor_sync(0xffffffffu, aq, w);
        }
        if (lid == 0) { red[half][8] = a; red[half][9] = aq; }
    }
    __syncthreads();
    const float mean = red[half][8] * (1.f / DIM);
    const float var  = red[half][9] * (1.f / DIM) - mean * mean;
    const float inv  = rsqrtf(var + 1e-5f);

    const float4 gv0 = reinterpret_cast<const float4*>(gam)[lt * 2];
    const float4 gv1 = reinterpret_cast<const float4*>(gam)[lt * 2 + 1];
    const float4 bv0 = reinterpret_cast<const float4*>(bet)[lt * 2];
    const float4 bv1 = reinterpret_cast<const float4*>(bet)[lt * 2 + 1];
    uint4 u;
    u.x = pack2((xv0.x - mean) * inv * gv0.x + bv0.x, (xv0.y - mean) * inv * gv0.y + bv0.y);
    u.y = pack2((xv0.z - mean) * inv * gv0.z + bv0.z, (xv0.w - mean) * inv * gv0.w + bv0.w);
    u.z = pack2((xv1.x - mean) * inv * gv1.x + bv1.x, (xv1.y - mean) * inv * gv1.y + bv1.y);
    u.w = pack2((xv1.z - mean) * inv * gv1.z + bv1.z, (xv1.w - mean) * inv * gv1.w + bv1.w);
    *reinterpret_cast<uint4*>(y + (size_t)row * DIM + lt * 8) = u;
}

// ---------------------------------------------------------------------------
// fp16 GEMM (R7 config): 128x128 CTA, 8 warps (2x4), warp tile 64x32,
// k-chunk 64, 3-stage cp.async, occ 2. ONE barrier per k-iteration.
// mode: 0 = fp32 store, 1 = fp16 store, 2 = GEGLU pairs -> Ch FFI-wide
// ---------------------------------------------------------------------------
struct GemmB {
    const __half* W[3];
    const float* bias[3];
    const float* res[3];
    float* Cf[3];
    __half* Ch[3];
};

#define NSTG 3
#define AS_B 16384                 // A stage bytes (128 rows * 128B)
#define BS_B 16384                 // B stage bytes (64 rows * 256B)
#define GEMM_SMEM (NSTG * (AS_B + BS_B))   // 98304

__global__ __launch_bounds__(256, 2) void gemm_h(
    const __half* __restrict__ A, GemmB gb, int M, int N, int K, int mode)
{
    extern __shared__ char smc[];
    const int z = blockIdx.z;
    const __half* W   = gb.W[z];
    const float* bias = gb.bias[z];
    const float* res  = gb.res[z];
    float* Cf         = gb.Cf[z];
    __half* Ch        = gb.Ch[z];

    const int tid = threadIdx.x, warp = tid >> 5, lane = tid & 31;
    const int grp = lane >> 2, tig = lane & 3;
    const int wm = (warp & 1) * 64, wn = (warp >> 1) * 32;
    const int m0 = blockIdx.y << 7, n0 = blockIdx.x << 7;

    const uint32_t smem_u = (uint32_t)__cvta_generic_to_shared(smc);

    auto issue = [&](int ch, int slot) {
        const int k0 = ch << 6;
        const uint32_t ab = smem_u + slot * AS_B;
        #pragma unroll
        for (int i = 0; i < 4; i++) {
            const int idx = tid + i * 256;
            const int row = idx >> 3, c = idx & 7;
            int gr = m0 + row; if (gr >= M) gr = M - 1;
            cpa16(ab + row * 128 + ((c ^ (row & 7)) << 4),
                  A + (size_t)gr * K + k0 + c * 8, true);
        }
        const uint32_t bb = smem_u + NSTG * AS_B + slot * BS_B;
        #pragma unroll
        for (int i = 0; i < 4; i++) {
            const int idx = tid + i * 256;
            const int row = idx >> 4, c = idx & 15;
            cpa16(bb + row * 256 + ((c ^ (row & 7)) << 4),
                  W + (size_t)(k0 + row) * N + n0 + c * 8, true);
        }
        cpa_commit();
    };

    float acc[4][4][4];
    #pragma unroll
    for (int i = 0; i < 4; i++)
        #pragma unroll
        for (int j = 0; j < 4; j++)
            #pragma unroll
            for (int r = 0; r < 4; r++) acc[i][j][r] = 0.f;

    const int nch = K >> 6;
    issue(0, 0); issue(1, 1);

    for (int it = 0; it < nch; it++) {
        if (it + 1 < nch) cpa_wait<1>(); else cpa_wait<0>();
        __syncthreads();
        if (it + 2 < nch) issue(it + 2, (it + 2) % 3);

        const int slot = it % 3;
        const uint32_t ab = smem_u + slot * AS_B;
        const uint32_t bb = smem_u + NSTG * AS_B + slot * BS_B;

        #pragma unroll
        for (int ks = 0; ks < 4; ks++) {
            unsigned a[4][4];
            #pragma unroll
            for (int mi = 0; mi < 4; mi++) {
                const int row = wm + mi * 16 + (lane & 15);
                const int ch = ks * 2 + (lane >> 4);
                ldsm_x4(a[mi], ab + row * 128 + ((ch ^ (row & 7)) << 4));
            }
            unsigned b[2][4];
            #pragma unroll
            for (int njp = 0; njp < 2; njp++) {
                const int krow = ks * 16 + (lane & 15);
                const int cn = (wn >> 3) + njp * 2 + (lane >> 4);
                ldsm_x4_t(b[njp], bb + krow * 256 + ((cn ^ (krow & 7)) << 4));
            }
            #pragma unroll
            for (int mi = 0; mi < 4; mi++)
                #pragma unroll
                for (int njp = 0; njp < 2; njp++) {
                    mma_h(acc[mi][njp * 2 + 0], a[mi], b[njp] + 0);
                    mma_h(acc[mi][njp * 2 + 1], a[mi], b[njp] + 2);
                }
        }
        // no bottom __syncthreads — next iteration's top barrier suffices.
    }

    #pragma unroll
    for (int mi = 0; mi < 4; mi++) {
        #pragma unroll
        for (int half = 0; half < 2; half++) {
            const int r = m0 + wm + mi * 16 + grp + half * 8;
            if (r >= M) continue;
            #pragma unroll
            for (int nj = 0; nj < 4; nj++) {
                const int c = n0 + wn + nj * 8 + tig * 2;
                float2 v;
                v.x = acc[mi][nj][half * 2 + 0];
                v.y = acc[mi][nj][half * 2 + 1];
                if (bias) { v.x += bias[c]; v.y += bias[c + 1]; }
                if (mode == 2) {
                    Ch[(size_t)r * FFI + (c >> 1)] = __float2half_rn(v.x * gelu_tanh(v.y));
                } else if (mode == 1) {
                    unsigned u = pack2(v.x, v.y);
                    *reinterpret_cast<unsigned*>(Ch + (size_t)r * N + c) = u;
                } else {
                    if (res) {
                        const float2 rv =
                            *reinterpret_cast<const float2*>(res + (size_t)r * N + c);
                        v.x += rv.x; v.y += rv.y;
                    }
                    *reinterpret_cast<float2*>(Cf + (size_t)r * N + c) = v;
                }
            }
        }
    }
}

// ---------------------------------------------------------------------------
// fp16 flash attention: 4 warps, 128 q/CTA, 32 q/warp (2 m16 tiles).
// 128-key smem tiles (two 64-key sub-tiles per barrier), double buffered.
// smem: Qs/Ps 16KB @0 ; KV slots 2x32KB @16384 (K 16KB + V 16KB each).
// Total 80KB, occ 2.
// ---------------------------------------------------------------------------
#define ATTN_SMEM 81920

__global__ __launch_bounds__(128, 2) void attn_h(
    const __half* __restrict__ Q, const __half* __restrict__ K,
    const __half* __restrict__ V, __half* __restrict__ O, int Sq, int Sk)
{
    extern __shared__ char smc[];
    const int tid = threadIdx.x, warp = tid >> 5, lane = tid & 31;
    const int grp = lane >> 2, tig = lane & 3;
    const int h = blockIdx.y, b = blockIdx.z;
    const int q0 = blockIdx.x * 128;
    const size_t qoff = (size_t)b * Sq * DIM + (size_t)h * DHEAD;
    const size_t koff = (size_t)b * Sk * DIM + (size_t)h * DHEAD;
    const int rbase = warp * 32;

    const uint32_t smem_u = (uint32_t)__cvta_generic_to_shared(smc);

    // 128-key tile load: K rows then V rows (each 128 rows x 128B)
    auto issue_kv = [&](int kt, int slot) {
        const uint32_t kb = smem_u + 16384 + slot * 32768;
        #pragma unroll
        for (int i = 0; i < 8; i++) {
            const int c = tid + i * 128;
            const int row = c >> 3, nc = c & 7;
            const int gr = kt * 128 + row;
            const bool ok = gr < Sk;
            const int grc = ok ? gr : 0;
            cpa16(kb + row * 128 + ((nc ^ (row & 7)) << 4),
                  K + koff + (size_t)grc * DIM + nc * 8, ok);
        }
        const uint32_t vb = kb + 16384;
        #pragma unroll
        for (int i = 0; i < 8; i++) {
            const int c = tid + i * 128;
            const int row = c >> 3, nc = c & 7;
            const int gr = kt * 128 + row;
            const bool ok = gr < Sk;
            const int grc = ok ? gr : 0;
            cpa16(vb + row * 128 + ((nc ^ (row & 7)) << 4),
                  V + koff + (size_t)grc * DIM + nc * 8, ok);
        }
        cpa_commit();
    };

    // Q tile load (scale pre-folded into wq)
    #pragma unroll
    for (int i = 0; i < 8; i++) {
        const int c = tid + i * 128;
        const int row = c >> 3, nc = c & 7;
        cpa16(smem_u + row * 128 + ((nc ^ (row & 7)) << 4),
              Q + qoff + (size_t)(q0 + row) * DIM + nc * 8, true);
    }
    cpa_commit();
    issue_kv(0, 0);

    unsigned qa[2][4][4];
    float o[2][8][4];
    #pragma unroll
    for (int t = 0; t < 2; t++)
        #pragma unroll
        for (int d = 0; d < 8; d++)
            #pragma unroll
            for (int r = 0; r < 4; r++) o[t][d][r] = 0.f;
    float mxA[2] = {-1e30f, -1e30f}, mxB[2] = {-1e30f, -1e30f};
    float lA[2] = {0.f, 0.f}, lB[2] = {0.f, 0.f};

    const int nkt = (Sk + 127) >> 7;
    for (int kt = 0; kt < nkt; kt++) {
        cpa_wait<0>();
        __syncthreads();
        if (kt + 1 < nkt) issue_kv(kt + 1, (kt + 1) & 1);

        if (kt == 0) {   // Q frags to registers (warp-private rows)
            #pragma unroll
            for (int t = 0; t < 2; t++)
                #pragma unroll
                for (int ks = 0; ks < 4; ks++) {
                    const int row = rbase + t * 16 + (lane & 15);
                    const int ch = ks * 2 + (lane >> 4);
                    ldsm_x4(qa[t][ks], smem_u + row * 128 + ((ch ^ (row & 7)) << 4));
                }
        }

        const uint32_t kvb = smem_u + 16384 + (kt & 1) * 32768;

        #pragma unroll
        for (int hf = 0; hf < 2; hf++) {
            const uint32_t ksl = kvb + hf * 8192;
            const uint32_t vsl = kvb + 16384 + hf * 8192;
            const int jb = kt * 128 + hf * 64;

            // ---- S = Q K^T (64-key sub-tile) ----
            float sc[2][8][4];
            #pragma unroll
            for (int t = 0; t < 2; t++)
                #pragma unroll
                for (int nj = 0; nj < 8; nj++)
                    #pragma unroll
                    for (int r = 0; r < 4; r++) sc[t][nj][r] = 0.f;

            #pragma unroll
            for (int ks = 0; ks < 4; ks++) {
                #pragma unroll
                for (int njp = 0; njp < 4; njp++) {
                    unsigned kb[4];
                    const int nrow = njp * 16 + (lane & 7) + (lane >> 4) * 8;
                    const int kc = ks * 2 + ((lane >> 3) & 1);
                    ldsm_x4(kb, ksl + nrow * 128 + ((kc ^ (nrow & 7)) << 4));
                    #pragma unroll
                    for (int t = 0; t < 2; t++) {
                        mma_h(sc[t][njp * 2 + 0], qa[t][ks], kb + 0);
                        mma_h(sc[t][njp * 2 + 1], qa[t][ks], kb + 2);
                    }
                }
            }

            // mask padded keys
            if (jb + 64 > Sk) {
                #pragma unroll
                for (int t = 0; t < 2; t++)
                    #pragma unroll
                    for (int nj = 0; nj < 8; nj++) {
                        const int j = jb + nj * 8 + tig * 2;
                        if (j     >= Sk) { sc[t][nj][0] = -1e30f; sc[t][nj][2] = -1e30f; }
                        if (j + 1 >= Sk) { sc[t][nj][1] = -1e30f; sc[t][nj][3] = -1e30f; }
                    }
            }

            // ---- online softmax ----
            #pragma unroll
            for (int t = 0; t < 2; t++) {
                float tm0 = -1e30f, tm1 = -1e30f;
                #pragma unroll
                for (int nj = 0; nj < 8; nj++) {
                    tm0 = fmaxf(tm0, fmaxf(sc[t][nj][0], sc[t][nj][1]));
                    tm1 = fmaxf(tm1, fmaxf(sc[t][nj][2], sc[t][nj][3]));
                }
                tm0 = fmaxf(tm0, __shfl_xor_sync(0xffffffffu, tm0, 1));
                tm0 = fmaxf(tm0, __shfl_xor_sync(0xffffffffu, tm0, 2));
                tm1 = fmaxf(tm1, __shfl_xor_sync(0xffffffffu, tm1, 1));
                tm1 = fmaxf(tm1, __shfl_xor_sync(0xffffffffu, tm1, 2));
                const float mn0 = fmaxf(mxA[t], tm0), mn1 = fmaxf(mxB[t], tm1);
                const float c0 = __expf(mxA[t] - mn0), c1 = __expf(mxB[t] - mn1);
                mxA[t] = mn0; mxB[t] = mn1;
                float s0 = 0.f, s1 = 0.f;
                #pragma unroll
                for (int nj = 0; nj < 8; nj++) {
                    sc[t][nj][0] = __expf(sc[t][nj][0] - mn0);
                    sc[t][nj][1] = __expf(sc[t][nj][1] - mn0);
                    sc[t][nj][2] = __expf(sc[t][nj][2] - mn1);
                    sc[t][nj][3] = __expf(sc[t][nj][3] - mn1);
                    s0 += sc[t][nj][0] + sc[t][nj][1];
                    s1 += sc[t][nj][2] + sc[t][nj][3];
                }
                s0 += __shfl_xor_sync(0xffffffffu, s0, 1);
                s0 += __shfl_xor_sync(0xffffffffu, s0, 2);
                s1 += __shfl_xor_sync(0xffffffffu, s1, 1);
                s1 += __shfl_xor_sync(0xffffffffu, s1, 2);
                lA[t] = lA[t] * c0 + s0;
                lB[t] = lB[t] * c1 + s1;
                #pragma unroll
                for (int d = 0; d < 8; d++) {
                    o[t][d][0] *= c0; o[t][d][1] *= c0;
                    o[t][d][2] *= c1; o[t][d][3] *= c1;
                }
            }

            // ---- publish P (half) to warp-private Ps rows (aliases Qs) ----
            #pragma unroll
            for (int t = 0; t < 2; t++)
                #pragma unroll
                for (int nj = 0; nj < 8; nj++) {
                    const int r0 = rbase + t * 16 + grp;
                    *reinterpret_cast<unsigned*>(smc + r0 * 128 +
                        ((nj ^ (r0 & 7)) << 4) + tig * 4) = pack2(sc[t][nj][0], sc[t][nj][1]);
                    const int r1 = r0 + 8;
                    *reinterpret_cast<unsigned*>(smc + r1 * 128 +
                        ((nj ^ (r1 & 7)) << 4) + tig * 4) = pack2(sc[t][nj][2], sc[t][nj][3]);
                }
            __syncwarp();

            // ---- O += P V ----
            #pragma unroll
            for (int kj = 0; kj < 4; kj++) {
                unsigned pa[2][4];
                #pragma unroll
                for (int t = 0; t < 2; t++) {
                    const int row = rbase + t * 16 + (lane & 15);
                    const int ch = kj * 2 + (lane >> 4);
                    ldsm_x4(pa[t], smem_u + row * 128 + ((ch ^ (row & 7)) << 4));
                }
                #pragma unroll
                for (int dgp = 0; dgp < 4; dgp++) {
                    unsigned vb[4];
                    const int vrow = kj * 16 + (lane & 15);
                    const int vc = dgp * 2 + (lane >> 4);
                    ldsm_x4_t(vb, vsl + vrow * 128 + ((vc ^ (vrow & 7)) << 4));
                    #pragma unroll
                    for (int t = 0; t < 2; t++) {
                        mma_h(o[t][dgp * 2 + 0], pa[t], vb + 0);
                        mma_h(o[t][dgp * 2 + 1], pa[t], vb + 2);
                    }
                }
            }
            __syncwarp();
        }
    }

    #pragma unroll
    for (int t = 0; t < 2; t++) {
        const float i0 = 1.f / lA[t], i1 = 1.f / lB[t];
        const int row0 = q0 + rbase + t * 16 + grp;
        #pragma unroll
        for (int d = 0; d < 8; d++) {
            *reinterpret_cast<unsigned*>(O + qoff + (size_t)row0 * DIM + d * 8 + tig * 2) =
                pack2(o[t][d][0] * i0, o[t][d][1] * i0);
            *reinterpret_cast<unsigned*>(O + qoff + (size_t)(row0 + 8) * DIM + d * 8 + tig * 2) =
                pack2(o[t][d][2] * i1, o[t][d][3] * i1);
        }
    }
}

// ---------------------------------------------------------------------------
extern "C" void kernel_launch(void* const* d_in, const int* in_sizes, int n_in,
                              void* d_out, int out_size)
{
    const float* hs   = (const float*)d_in[0];
    const float* ctx  = (const float*)d_in[1];
    const float* wq1  = (const float*)d_in[2];
    const float* wk1  = (const float*)d_in[3];
    const float* wv1  = (const float*)d_in[4];
    const float* wo1  = (const float*)d_in[5];
    const float* bo1  = (const float*)d_in[6];
    const float* wq2  = (const float*)d_in[7];
    const float* wk2  = (const float*)d_in[8];
    const float* wv2  = (const float*)d_in[9];
    const float* wo2  = (const float*)d_in[10];
    const float* bo2  = (const float*)d_in[11];
    const float* wff1 = (const float*)d_in[12];
    const float* bff1 = (const float*)d_in[13];
    const float* wff2 = (const float*)d_in[14];
    const float* bff2 = (const float*)d_in[15];
    const float* ln1g = (const float*)d_in[16];
    const float* ln1b = (const float*)d_in[17];
    const float* ln2g = (const float*)d_in[18];
    const float* ln2b = (const float*)d_in[19];
    const float* ln3g = (const float*)d_in[20];
    const float* ln3b = (const float*)d_in[21];
    float* out = (float*)d_out;

    __half *xn, *q, *k, *v, *ah, *gg, *wh;
    float *h, *bf1;
    cudaGetSymbolAddress((void**)&xn,  g_xnh);
    cudaGetSymbolAddress((void**)&q,   g_qh);
    cudaGetSymbolAddress((void**)&k,   g_kh);
    cudaGetSymbolAddress((void**)&v,   g_vh);
    cudaGetSymbolAddress((void**)&ah,  g_ah);
    cudaGetSymbolAddress((void**)&gg,  g_ggh);
    cudaGetSymbolAddress((void**)&wh,  g_wh);
    cudaGetSymbolAddress((void**)&h,   g_h);
    cudaGetSymbolAddress((void**)&bf1, g_bf1);

    // one-time infra (streams/events are host resources, not device allocs)
    static bool init_done = false;
    static cudaStream_t s2;
    static cudaEvent_t evRoot, evE, evL, evAT, evKV;
    if (!init_done) {
        cudaFuncSetAttribute(gemm_h, cudaFuncAttributeMaxDynamicSharedMemorySize, GEMM_SMEM);
        cudaFuncSetAttribute(attn_h, cudaFuncAttributeMaxDynamicSharedMemorySize, ATTN_SMEM);
        cudaStreamCreateWithFlags(&s2, cudaStreamNonBlocking);
        cudaEventCreateWithFlags(&evRoot, cudaEventDisableTiming);
        cudaEventCreateWithFlags(&evE,    cudaEventDisableTiming);
        cudaEventCreateWithFlags(&evL,    cudaEventDisableTiming);
        cudaEventCreateWithFlags(&evAT,   cudaEventDisableTiming);
        cudaEventCreateWithFlags(&evKV,   cudaEventDisableTiming);
        init_done = true;
    }

    // ---- weight-conversion job tables ----
    CJobs cjE;
    {
        const float* s[3] = {wq1, wk1, wv1};
        const int    o[3] = {OWQ1, OWK1, OWV1};
        for (int i = 0; i < 3; i++) {
            cjE.src[i] = s[i]; cjE.dst[i] = wh + o[i]; cjE.n[i] = 1048576;
            cjE.scale[i] = (i == 0) ? 0.125f : 1.0f;
        }
    }
    CJobs cjL;
    {
        const float* s[7] = {wo1, wq2, wk2, wv2, wo2, wff2, ctx};
        const int    o[7] = {OWO1, OWQ2, OWK2, OWV2, OWO2, OWF2, OCTX};
        const int    n[7] = {1048576, 1048576, 786432, 786432, 1048576, 4194304, 236544};
        for (int i = 0; i < 7; i++) {
            cjL.src[i] = s[i]; cjL.dst[i] = wh + o[i]; cjL.n[i] = n[i];
            cjL.scale[i] = (i == 1) ? 0.125f : 1.0f;
        }
    }

    const dim3 blk(256);
    const dim3 ablk(128);
    const dim3 g_attng(SEQ / 128, NHEADS, 4);
    const dim3 lngrid(BROWS / 2);

    GemmB gqkv{}, gwo1{}, gq2{}, gkv2{}, gwo2{}, gff1{}, gff2{};
    gqkv.W[0] = wh + OWQ1; gqkv.Ch[0] = q;
    gqkv.W[1] = wh + OWK1; gqkv.Ch[1] = k;
    gqkv.W[2] = wh + OWV1; gqkv.Ch[2] = v;
    gwo1.W[0] = wh + OWO1; gwo1.bias[0] = bo1; gwo1.res[0] = hs; gwo1.Cf[0] = h;
    gq2.W[0]  = wh + OWQ2; gq2.Ch[0]  = q;
    gkv2.W[0] = wh + OWK2; gkv2.Ch[0] = k;
    gkv2.W[1] = wh + OWV2; gkv2.Ch[1] = v;
    gwo2.W[0] = wh + OWO2; gwo2.bias[0] = bo2; gwo2.res[0] = h; gwo2.Cf[0] = h;
    gff1.W[0] = wh + OWF1; gff1.bias[0] = bf1; gff1.Ch[0] = gg;
    gff2.W[0] = wh + OWF2; gff2.bias[0] = bff2; gff2.res[0] = h; gff2.Cf[0] = out;

    // ---- fork stream 2 into the (captured) main stream's graph ----
    cudaEventRecord(evRoot, 0);
    cudaStreamWaitEvent(s2, evRoot, 0);

    // s2: early conversion (QKV weights), then the late bulk + FF1 permutes
    conv_kernel<<<dim3(256, 3), blk, 0, s2>>>(cjE);
    cudaEventRecord(evE, s2);
    conv_kernel<<<dim3(512, 7), blk, 0, s2>>>(cjL);
    permute_ff1<<<dim3(16, 1024), blk, 0, s2>>>(wff1, wh + OWF1);
    permute_bias_ff1<<<dim3(16), blk, 0, s2>>>(bff1, bf1);
    cudaEventRecord(evL, s2);

    // ---- main: self-attention block (overlaps late conversion) ----
    ln_kernel<<<lngrid, blk>>>(hs, xn, ln1g, ln1b);
    cudaStreamWaitEvent(0, evE, 0);
    gemm_h<<<dim3(8, 64, 3), blk, GEMM_SMEM>>>(xn, gqkv, BROWS, DIM, DIM, 1);
    attn_h<<<g_attng, ablk, ATTN_SMEM>>>(q, k, v, ah, SEQ, SEQ);
    cudaEventRecord(evAT, 0);

    // s2: kv2 GEMM (needs late conv + self-attn done w/ k,v buffers)
    cudaStreamWaitEvent(s2, evAT, 0);
    gemm_h<<<dim3(8, 3, 2), blk, GEMM_SMEM, s2>>>(wh + OCTX, gkv2, CROWS, DIM, CTXD, 1);
    cudaEventRecord(evKV, s2);

    // main: WO1 + cross-attention chain (kv2 overlaps WO1/ln2/q2)
    cudaStreamWaitEvent(0, evL, 0);
    gemm_h<<<dim3(8, 64, 1), blk, GEMM_SMEM>>>(ah, gwo1, BROWS, DIM, DIM, 0);
    ln_kernel<<<lngrid, blk>>>(h, xn, ln2g, ln2b);
    gemm_h<<<dim3(8, 64, 1), blk, GEMM_SMEM>>>(xn, gq2, BROWS, DIM, DIM, 1);
    cudaStreamWaitEvent(0, evKV, 0);
    attn_h<<<g_attng, ablk, ATTN_SMEM>>>(q, k, v, ah, SEQ, TCTX);
    gemm_h<<<dim3(8, 64, 1), blk, GEMM_SMEM>>>(ah, gwo2, BROWS, DIM, DIM, 0);

    // ---- GEGLU feed-forward (fused into FF1 epilogue) ----
    ln_kernel<<<lngrid, blk>>>(h, xn, ln3g, ln3b);
    gemm_h<<<dim3(64, 64, 1), blk, GEMM_SMEM>>>(xn, gff1, BROWS, 2 * FFI, DIM, 2);
    gemm_h<<<dim3(8, 64, 1), blk, GEMM_SMEM>>>(gg, gff2, BROWS, DIM, FFI, 0);
}

// round 13
// speedup vs baseline: 1.1885x; 1.0216x over previous
#include <cuda_runtime.h>
#include <cuda_fp16.h>
#include <cstdint>
#include <cstddef>

// ---------------------------------------------------------------------------
#define BROWS   8192
#define CROWS   308
#define DIM     1024
#define CTXD    768
#define FFI     4096
#define SEQ     2048
#define TCTX    77
#define NHEADS  16
#define DHEAD   64

// ---------------------------------------------------------------------------
// Scratch
// ---------------------------------------------------------------------------
__device__ __half g_xnh[(size_t)BROWS * DIM];
__device__ __half g_qh [(size_t)BROWS * DIM];
__device__ __half g_kh [(size_t)BROWS * DIM];
__device__ __half g_vh [(size_t)BROWS * DIM];
__device__ __half g_ah [(size_t)BROWS * DIM];
__device__ __half g_ggh[(size_t)BROWS * FFI];
__device__ float  g_h  [(size_t)BROWS * DIM];

// half weights + context; wff1 column-interleaved (lin,gate); wff2 row-permuted
#define OWQ1 0
#define OWK1 1048576
#define OWV1 2097152
#define OWO1 3145728
#define OWQ2 4194304
#define OWK2 5242880
#define OWV2 6029312
#define OWO2 6815744
#define OWF1 7864320
#define OWF2 16252928
#define OCTX 20447232
#define WHTOT 20683776
__device__ __half g_wh[WHTOT];
__device__ float  g_bf1[2 * FFI];   // permuted FF1 bias (fp32)

// ---------------------------------------------------------------------------
// helpers
// ---------------------------------------------------------------------------
__device__ __forceinline__ void mma_h(float c[4], const unsigned a[4], const unsigned b[2]) {
    asm volatile(
        "mma.sync.aligned.m16n8k16.row.col.f32.f16.f16.f32 "
        "{%0,%1,%2,%3}, {%4,%5,%6,%7}, {%8,%9}, {%0,%1,%2,%3};\n"
        : "+f"(c[0]), "+f"(c[1]), "+f"(c[2]), "+f"(c[3])
        : "r"(a[0]), "r"(a[1]), "r"(a[2]), "r"(a[3]), "r"(b[0]), "r"(b[1]));
}
__device__ __forceinline__ void ldsm_x4(unsigned r[4], uint32_t addr) {
    asm volatile("ldmatrix.sync.aligned.m8n8.x4.shared.b16 {%0,%1,%2,%3}, [%4];"
                 : "=r"(r[0]), "=r"(r[1]), "=r"(r[2]), "=r"(r[3]) : "r"(addr));
}
__device__ __forceinline__ void ldsm_x4_t(unsigned r[4], uint32_t addr) {
    asm volatile("ldmatrix.sync.aligned.m8n8.x4.trans.shared.b16 {%0,%1,%2,%3}, [%4];"
                 : "=r"(r[0]), "=r"(r[1]), "=r"(r[2]), "=r"(r[3]) : "r"(addr));
}
__device__ __forceinline__ void cpa16(uint32_t dst, const void* src, bool pred) {
    int sz = pred ? 16 : 0;
    asm volatile("cp.async.cg.shared.global [%0], [%1], 16, %2;\n"
                 :: "r"(dst), "l"(src), "r"(sz));
}
__device__ __forceinline__ void cpa_commit() { asm volatile("cp.async.commit_group;"); }
template<int N> __device__ __forceinline__ void cpa_wait() {
    asm volatile("cp.async.wait_group %0;" :: "n"(N));
}
__device__ __forceinline__ float tanh_fast(float x) {
    float y; asm("tanh.approx.f32 %0, %1;" : "=f"(y) : "f"(x));
    return y;
}
__device__ __forceinline__ float gelu_tanh(float x) {
    const float x3 = x * x * x;
    return 0.5f * x * (1.f + tanh_fast(0.7978845608028654f * (x + 0.044715f * x3)));
}
__device__ __forceinline__ unsigned pack2(float a, float b) {
    __half2 h = __floats2half2_rn(a, b);
    return *reinterpret_cast<unsigned*>(&h);
}

// ---------------------------------------------------------------------------
// fp32 -> fp16 conversion pass (scale folds 0.125 into wq)
// ---------------------------------------------------------------------------
struct CJobs { const float* src[6]; __half* dst[6]; int n[6]; float scale[6]; };

__global__ __launch_bounds__(256) void conv_kernel(CJobs j) {
    const int job = blockIdx.y;
    const float* s = j.src[job];
    __half* d = j.dst[job];
    const int n = j.n[job];
    const float sc = j.scale[job];
    for (int i = (blockIdx.x * 256 + threadIdx.x) * 4; i < n; i += gridDim.x * 1024) {
        float4 v = *reinterpret_cast<const float4*>(s + i);
        uint2 u;
        u.x = pack2(v.x * sc, v.y * sc);
        u.y = pack2(v.z * sc, v.w * sc);
        *reinterpret_cast<uint2*>(d + i) = u;
    }
}

// Interleave wff1 columns: dst[k][2j]=lin col j, dst[k][2j+1]=gate col (j+FFI)
__global__ __launch_bounds__(256) void permute_ff1(
    const float* __restrict__ s, __half* __restrict__ d)
{
    const int k = blockIdx.y;
    const int j = blockIdx.x * 256 + threadIdx.x;
    const float lin = s[(size_t)k * (2 * FFI) + j];
    const float gt  = s[(size_t)k * (2 * FFI) + FFI + j];
    unsigned u = pack2(lin, gt);
    *reinterpret_cast<unsigned*>(d + (size_t)k * (2 * FFI) + 2 * j) = u;
}

__global__ __launch_bounds__(256) void permute_bias_ff1(
    const float* __restrict__ s, float* __restrict__ d)
{
    const int j = blockIdx.x * 256 + threadIdx.x;
    float2 v; v.x = s[j]; v.y = s[FFI + j];
    *reinterpret_cast<float2*>(d + 2 * j) = v;
}

// wff2 row permutation matching gg's packed-store column order:
// phi(p): within each 16-row group, (a,b) -> (b,a) on p = G*16 + a*4 + b.
// dst[p][n] = half(src[phi(p)][n]); phi is an involution.
__global__ __launch_bounds__(256) void permute_ff2(
    const float* __restrict__ s, __half* __restrict__ d)
{
    const int p = blockIdx.y;
    const int src_row = (p & ~15) | ((p & 3) << 2) | ((p >> 2) & 3);
    const int c = (blockIdx.x * 256 + threadIdx.x) * 4;
    const float4 v = *reinterpret_cast<const float4*>(s + (size_t)src_row * DIM + c);
    uint2 u;
    u.x = pack2(v.x, v.y);
    u.y = pack2(v.z, v.w);
    *reinterpret_cast<uint2*>(d + (size_t)p * DIM + c) = u;
}

// ---------------------------------------------------------------------------
// LayerNorm v2: 2 rows per block, 128 threads/row (8 elems/thread).
// ---------------------------------------------------------------------------
__global__ __launch_bounds__(256) void ln_kernel(
    const float* __restrict__ x, __half* __restrict__ y,
    const float* __restrict__ gam, const float* __restrict__ bet)
{
    __shared__ float red[2][10];
    const int half = threadIdx.x >> 7;
    const int lt   = threadIdx.x & 127;
    const int row  = blockIdx.x * 2 + half;
    const int wid  = lt >> 5, lid = lt & 31;

    const float4 xv0 = reinterpret_cast<const float4*>(x + (size_t)row * DIM)[lt * 2];
    const float4 xv1 = reinterpret_cast<const float4*>(x + (size_t)row * DIM)[lt * 2 + 1];

    float s  = xv0.x + xv0.y + xv0.z + xv0.w + xv1.x + xv1.y + xv1.z + xv1.w;
    float sq = xv0.x*xv0.x + xv0.y*xv0.y + xv0.z*xv0.z + xv0.w*xv0.w
             + xv1.x*xv1.x + xv1.y*xv1.y + xv1.z*xv1.z + xv1.w*xv1.w;
    #pragma unroll
    for (int w = 16; w > 0; w >>= 1) {
        s  += __shfl_xor_sync(0xffffffffu, s,  w);
        sq += __shfl_xor_sync(0xffffffffu, sq, w);
    }
    if (lid == 0) { red[half][wid] = s; red[half][4 + wid] = sq; }
    __syncthreads();
    if (lt < 32) {
        float a  = (lid < 4) ? red[half][lid]     : 0.f;
        float aq = (lid < 4) ? red[half][4 + lid] : 0.f;
        #pragma unroll
        for (int w = 2; w > 0; w >>= 1) {
            a  += __shfl_xor_sync(0xffffffffu, a,  w);
            aq += __shfl_xor_sync(0xffffffffu, aq, w);
        }
        if (lid == 0) { red[half][8] = a; red[half][9] = aq; }
    }
    __syncthreads();
    const float mean = red[half][8] * (1.f / DIM);
    const float var  = red[half][9] * (1.f / DIM) - mean * mean;
    const float inv  = rsqrtf(var + 1e-5f);

    const float4 gv0 = reinterpret_cast<const float4*>(gam)[lt * 2];
    const float4 gv1 = reinterpret_cast<const float4*>(gam)[lt * 2 + 1];
    const float4 bv0 = reinterpret_cast<const float4*>(bet)[lt * 2];
    const float4 bv1 = reinterpret_cast<const float4*>(bet)[lt * 2 + 1];
    uint4 u;
    u.x = pack2((xv0.x - mean) * inv * gv0.x + bv0.x, (xv0.y - mean) * inv * gv0.y + bv0.y);
    u.y = pack2((xv0.z - mean) * inv * gv0.z + bv0.z, (xv0.w - mean) * inv * gv0.w + bv0.w);
    u.z = pack2((xv1.x - mean) * inv * gv1.x + bv1.x, (xv1.y - mean) * inv * gv1.y + bv1.y);
    u.w = pack2((xv1.z - mean) * inv * gv1.z + bv1.z, (xv1.w - mean) * inv * gv1.w + bv1.w);
    *reinterpret_cast<uint4*>(y + (size_t)row * DIM + lt * 8) = u;
}

// ---------------------------------------------------------------------------
// fp16 GEMM: 128x128 CTA, 8 warps (2x4), warp tile 64x32, k-chunk 64,
// 3-stage cp.async, occ 2. ONE barrier per k-iteration.
// mode: 0 = fp32 store, 1 = fp16 store, 2 = GEGLU packed pairs -> Ch FFI-wide
// ---------------------------------------------------------------------------
struct GemmB {
    const __half* W[3];
    const float* bias[3];
    const float* res[3];
    float* Cf[3];
    __half* Ch[3];
};

#define NSTG 3
#define AS_B 16384
#define BS_B 16384
#define GEMM_SMEM (NSTG * (AS_B + BS_B))   // 98304

__global__ __launch_bounds__(256, 2) void gemm_h(
    const __half* __restrict__ A, GemmB gb, int M, int N, int K, int mode)
{
    extern __shared__ char smc[];
    const int z = blockIdx.z;
    const __half* W   = gb.W[z];
    const float* bias = gb.bias[z];
    const float* res  = gb.res[z];
    float* Cf         = gb.Cf[z];
    __half* Ch        = gb.Ch[z];

    const int tid = threadIdx.x, warp = tid >> 5, lane = tid & 31;
    const int grp = lane >> 2, tig = lane & 3;
    const int wm = (warp & 1) * 64, wn = (warp >> 1) * 32;
    const int m0 = blockIdx.y << 7, n0 = blockIdx.x << 7;

    const uint32_t smem_u = (uint32_t)__cvta_generic_to_shared(smc);

    auto issue = [&](int ch, int slot) {
        const int k0 = ch << 6;
        const uint32_t ab = smem_u + slot * AS_B;
        #pragma unroll
        for (int i = 0; i < 4; i++) {
            const int idx = tid + i * 256;
            const int row = idx >> 3, c = idx & 7;
            int gr = m0 + row; if (gr >= M) gr = M - 1;
            cpa16(ab + row * 128 + ((c ^ (row & 7)) << 4),
                  A + (size_t)gr * K + k0 + c * 8, true);
        }
        const uint32_t bb = smem_u + NSTG * AS_B + slot * BS_B;
        #pragma unroll
        for (int i = 0; i < 4; i++) {
            const int idx = tid + i * 256;
            const int row = idx >> 4, c = idx & 15;
            cpa16(bb + row * 256 + ((c ^ (row & 7)) << 4),
                  W + (size_t)(k0 + row) * N + n0 + c * 8, true);
        }
        cpa_commit();
    };

    float acc[4][4][4];
    #pragma unroll
    for (int i = 0; i < 4; i++)
        #pragma unroll
        for (int j = 0; j < 4; j++)
            #pragma unroll
            for (int r = 0; r < 4; r++) acc[i][j][r] = 0.f;

    const int nch = K >> 6;
    issue(0, 0); issue(1, 1);

    for (int it = 0; it < nch; it++) {
        if (it + 1 < nch) cpa_wait<1>(); else cpa_wait<0>();
        __syncthreads();
        if (it + 2 < nch) issue(it + 2, (it + 2) % 3);

        const int slot = it % 3;
        const uint32_t ab = smem_u + slot * AS_B;
        const uint32_t bb = smem_u + NSTG * AS_B + slot * BS_B;

        #pragma unroll
        for (int ks = 0; ks < 4; ks++) {
            unsigned a[4][4];
            #pragma unroll
            for (int mi = 0; mi < 4; mi++) {
                const int row = wm + mi * 16 + (lane & 15);
                const int ch = ks * 2 + (lane >> 4);
                ldsm_x4(a[mi], ab + row * 128 + ((ch ^ (row & 7)) << 4));
            }
            unsigned b[2][4];
            #pragma unroll
            for (int njp = 0; njp < 2; njp++) {
                const int krow = ks * 16 + (lane & 15);
                const int cn = (wn >> 3) + njp * 2 + (lane >> 4);
                ldsm_x4_t(b[njp], bb + krow * 256 + ((cn ^ (krow & 7)) << 4));
            }
            #pragma unroll
            for (int mi = 0; mi < 4; mi++)
                #pragma unroll
                for (int njp = 0; njp < 2; njp++) {
                    mma_h(acc[mi][njp * 2 + 0], a[mi], b[njp] + 0);
                    mma_h(acc[mi][njp * 2 + 1], a[mi], b[njp] + 2);
                }
        }
        // no bottom __syncthreads — next iteration's top barrier suffices.
    }

    if (mode == 2) {
        // GEGLU epilogue with packed stores. Thread (grp,tig), warp wn, nj=0..3
        // produce 4 outputs at physical cols n0/2 + wn/2 + tig*4 + nj
        // (column permutation phi baked into wff2 rows at prep).
        #pragma unroll
        for (int mi = 0; mi < 4; mi++) {
            #pragma unroll
            for (int half = 0; half < 2; half++) {
                const int r = m0 + wm + mi * 16 + grp + half * 8;
                if (r >= M) continue;
                __half hout[4];
                #pragma unroll
                for (int nj = 0; nj < 4; nj++) {
                    const int c = n0 + wn + nj * 8 + tig * 2;
                    const float2 bv = *reinterpret_cast<const float2*>(bias + c);
                    const float lx = acc[mi][nj][half * 2 + 0] + bv.x;
                    const float gx = acc[mi][nj][half * 2 + 1] + bv.y;
                    hout[nj] = __float2half_rn(lx * gelu_tanh(gx));
                }
                const int p0 = (n0 >> 1) + (wn >> 1) + tig * 4;
                *reinterpret_cast<uint2*>(Ch + (size_t)r * FFI + p0) =
                    *reinterpret_cast<uint2*>(hout);
            }
        }
    } else {
        #pragma unroll
        for (int mi = 0; mi < 4; mi++) {
            #pragma unroll
            for (int half = 0; half < 2; half++) {
                const int r = m0 + wm + mi * 16 + grp + half * 8;
                if (r >= M) continue;
                #pragma unroll
                for (int nj = 0; nj < 4; nj++) {
                    const int c = n0 + wn + nj * 8 + tig * 2;
                    float2 v;
                    v.x = acc[mi][nj][half * 2 + 0];
                    v.y = acc[mi][nj][half * 2 + 1];
                    if (bias) { v.x += bias[c]; v.y += bias[c + 1]; }
                    if (mode == 1) {
                        unsigned u = pack2(v.x, v.y);
                        *reinterpret_cast<unsigned*>(Ch + (size_t)r * N + c) = u;
                    } else {
                        if (res) {
                            const float2 rv =
                                *reinterpret_cast<const float2*>(res + (size_t)r * N + c);
                            v.x += rv.x; v.y += rv.y;
                        }
                        *reinterpret_cast<float2*>(Cf + (size_t)r * N + c) = v;
                    }
                }
            }
        }
    }
}

// ---------------------------------------------------------------------------
// fp16 flash attention: 4 warps, 128 q/CTA, 32 q/warp (2 m16 tiles).
// 128-key smem tiles (two 64-key sub-tiles per barrier), double buffered.
// smem 80KB, occ 2.
// ---------------------------------------------------------------------------
#define ATTN_SMEM 81920

__global__ __launch_bounds__(128, 2) void attn_h(
    const __half* __restrict__ Q, const __half* __restrict__ K,
    const __half* __restrict__ V, __half* __restrict__ O, int Sq, int Sk)
{
    extern __shared__ char smc[];
    const int tid = threadIdx.x, warp = tid >> 5, lane = tid & 31;
    const int grp = lane >> 2, tig = lane & 3;
    const int h = blockIdx.y, b = blockIdx.z;
    const int q0 = blockIdx.x * 128;
    const size_t qoff = (size_t)b * Sq * DIM + (size_t)h * DHEAD;
    const size_t koff = (size_t)b * Sk * DIM + (size_t)h * DHEAD;
    const int rbase = warp * 32;

    const uint32_t smem_u = (uint32_t)__cvta_generic_to_shared(smc);

    auto issue_kv = [&](int kt, int slot) {
        const uint32_t kb = smem_u + 16384 + slot * 32768;
        #pragma unroll
        for (int i = 0; i < 8; i++) {
            const int c = tid + i * 128;
            const int row = c >> 3, nc = c & 7;
            const int gr = kt * 128 + row;
            const bool ok = gr < Sk;
            const int grc = ok ? gr : 0;
            cpa16(kb + row * 128 + ((nc ^ (row & 7)) << 4),
                  K + koff + (size_t)grc * DIM + nc * 8, ok);
        }
        const uint32_t vb = kb + 16384;
        #pragma unroll
        for (int i = 0; i < 8; i++) {
            const int c = tid + i * 128;
            const int row = c >> 3, nc = c & 7;
            const int gr = kt * 128 + row;
            const bool ok = gr < Sk;
            const int grc = ok ? gr : 0;
            cpa16(vb + row * 128 + ((nc ^ (row & 7)) << 4),
                  V + koff + (size_t)grc * DIM + nc * 8, ok);
        }
        cpa_commit();
    };

    #pragma unroll
    for (int i = 0; i < 8; i++) {
        const int c = tid + i * 128;
        const int row = c >> 3, nc = c & 7;
        cpa16(smem_u + row * 128 + ((nc ^ (row & 7)) << 4),
              Q + qoff + (size_t)(q0 + row) * DIM + nc * 8, true);
    }
    cpa_commit();
    issue_kv(0, 0);

    unsigned qa[2][4][4];
    float o[2][8][4];
    #pragma unroll
    for (int t = 0; t < 2; t++)
        #pragma unroll
        for (int d = 0; d < 8; d++)
            #pragma unroll
            for (int r = 0; r < 4; r++) o[t][d][r] = 0.f;
    float mxA[2] = {-1e30f, -1e30f}, mxB[2] = {-1e30f, -1e30f};
    float lA[2] = {0.f, 0.f}, lB[2] = {0.f, 0.f};

    const int nkt = (Sk + 127) >> 7;
    for (int kt = 0; kt < nkt; kt++) {
        cpa_wait<0>();
        __syncthreads();
        if (kt + 1 < nkt) issue_kv(kt + 1, (kt + 1) & 1);

        if (kt == 0) {
            #pragma unroll
            for (int t = 0; t < 2; t++)
                #pragma unroll
                for (int ks = 0; ks < 4; ks++) {
                    const int row = rbase + t * 16 + (lane & 15);
                    const int ch = ks * 2 + (lane >> 4);
                    ldsm_x4(qa[t][ks], smem_u + row * 128 + ((ch ^ (row & 7)) << 4));
                }
        }

        const uint32_t kvb = smem_u + 16384 + (kt & 1) * 32768;

        #pragma unroll
        for (int hf = 0; hf < 2; hf++) {
            const uint32_t ksl = kvb + hf * 8192;
            const uint32_t vsl = kvb + 16384 + hf * 8192;
            const int jb = kt * 128 + hf * 64;

            float sc[2][8][4];
            #pragma unroll
            for (int t = 0; t < 2; t++)
                #pragma unroll
                for (int nj = 0; nj < 8; nj++)
                    #pragma unroll
                    for (int r = 0; r < 4; r++) sc[t][nj][r] = 0.f;

            #pragma unroll
            for (int ks = 0; ks < 4; ks++) {
                #pragma unroll
                for (int njp = 0; njp < 4; njp++) {
                    unsigned kb[4];
                    const int nrow = njp * 16 + (lane & 7) + (lane >> 4) * 8;
                    const int kc = ks * 2 + ((lane >> 3) & 1);
                    ldsm_x4(kb, ksl + nrow * 128 + ((kc ^ (nrow & 7)) << 4));
                    #pragma unroll
                    for (int t = 0; t < 2; t++) {
                        mma_h(sc[t][njp * 2 + 0], qa[t][ks], kb + 0);
                        mma_h(sc[t][njp * 2 + 1], qa[t][ks], kb + 2);
                    }
                }
            }

            if (jb + 64 > Sk) {
                #pragma unroll
                for (int t = 0; t < 2; t++)
                    #pragma unroll
                    for (int nj = 0; nj < 8; nj++) {
                        const int j = jb + nj * 8 + tig * 2;
                        if (j     >= Sk) { sc[t][nj][0] = -1e30f; sc[t][nj][2] = -1e30f; }
                        if (j + 1 >= Sk) { sc[t][nj][1] = -1e30f; sc[t][nj][3] = -1e30f; }
                    }
            }

            #pragma unroll
            for (int t = 0; t < 2; t++) {
                float tm0 = -1e30f, tm1 = -1e30f;
                #pragma unroll
                for (int nj = 0; nj < 8; nj++) {
                    tm0 = fmaxf(tm0, fmaxf(sc[t][nj][0], sc[t][nj][1]));
                    tm1 = fmaxf(tm1, fmaxf(sc[t][nj][2], sc[t][nj][3]));
                }
                tm0 = fmaxf(tm0, __shfl_xor_sync(0xffffffffu, tm0, 1));
                tm0 = fmaxf(tm0, __shfl_xor_sync(0xffffffffu, tm0, 2));
                tm1 = fmaxf(tm1, __shfl_xor_sync(0xffffffffu, tm1, 1));
                tm1 = fmaxf(tm1, __shfl_xor_sync(0xffffffffu, tm1, 2));
                const float mn0 = fmaxf(mxA[t], tm0), mn1 = fmaxf(mxB[t], tm1);
                const float c0 = __expf(mxA[t] - mn0), c1 = __expf(mxB[t] - mn1);
                mxA[t] = mn0; mxB[t] = mn1;
                float s0 = 0.f, s1 = 0.f;
                #pragma unroll
                for (int nj = 0; nj < 8; nj++) {
                    sc[t][nj][0] = __expf(sc[t][nj][0] - mn0);
                    sc[t][nj][1] = __expf(sc[t][nj][1] - mn0);
                    sc[t][nj][2] = __expf(sc[t][nj][2] - mn1);
                    sc[t][nj][3] = __expf(sc[t][nj][3] - mn1);
                    s0 += sc[t][nj][0] + sc[t][nj][1];
                    s1 += sc[t][nj][2] + sc[t][nj][3];
                }
                s0 += __shfl_xor_sync(0xffffffffu, s0, 1);
                s0 += __shfl_xor_sync(0xffffffffu, s0, 2);
                s1 += __shfl_xor_sync(0xffffffffu, s1, 1);
                s1 += __shfl_xor_sync(0xffffffffu, s1, 2);
                lA[t] = lA[t] * c0 + s0;
                lB[t] = lB[t] * c1 + s1;
                #pragma unroll
                for (int d = 0; d < 8; d++) {
                    o[t][d][0] *= c0; o[t][d][1] *= c0;
                    o[t][d][2] *= c1; o[t][d][3] *= c1;
                }
            }

            #pragma unroll
            for (int t = 0; t < 2; t++)
                #pragma unroll
                for (int nj = 0; nj < 8; nj++) {
                    const int r0 = rbase + t * 16 + grp;
                    *reinterpret_cast<unsigned*>(smc + r0 * 128 +
                        ((nj ^ (r0 & 7)) << 4) + tig * 4) = pack2(sc[t][nj][0], sc[t][nj][1]);
                    const int r1 = r0 + 8;
                    *reinterpret_cast<unsigned*>(smc + r1 * 128 +
                        ((nj ^ (r1 & 7)) << 4) + tig * 4) = pack2(sc[t][nj][2], sc[t][nj][3]);
                }
            __syncwarp();

            #pragma unroll
            for (int kj = 0; kj < 4; kj++) {
                unsigned pa[2][4];
                #pragma unroll
                for (int t = 0; t < 2; t++) {
                    const int row = rbase + t * 16 + (lane & 15);
                    const int ch = kj * 2 + (lane >> 4);
                    ldsm_x4(pa[t], smem_u + row * 128 + ((ch ^ (row & 7)) << 4));
                }
                #pragma unroll
                for (int dgp = 0; dgp < 4; dgp++) {
                    unsigned vb[4];
                    const int vrow = kj * 16 + (lane & 15);
                    const int vc = dgp * 2 + (lane >> 4);
                    ldsm_x4_t(vb, vsl + vrow * 128 + ((vc ^ (vrow & 7)) << 4));
                    #pragma unroll
                    for (int t = 0; t < 2; t++) {
                        mma_h(o[t][dgp * 2 + 0], pa[t], vb + 0);
                        mma_h(o[t][dgp * 2 + 1], pa[t], vb + 2);
                    }
                }
            }
            __syncwarp();
        }
    }

    #pragma unroll
    for (int t = 0; t < 2; t++) {
        const float i0 = 1.f / lA[t], i1 = 1.f / lB[t];
        const int row0 = q0 + rbase + t * 16 + grp;
        #pragma unroll
        for (int d = 0; d < 8; d++) {
            *reinterpret_cast<unsigned*>(O + qoff + (size_t)row0 * DIM + d * 8 + tig * 2) =
                pack2(o[t][d][0] * i0, o[t][d][1] * i0);
            *reinterpret_cast<unsigned*>(O + qoff + (size_t)(row0 + 8) * DIM + d * 8 + tig * 2) =
                pack2(o[t][d][2] * i1, o[t][d][3] * i1);
        }
    }
}

// ---------------------------------------------------------------------------
extern "C" void kernel_launch(void* const* d_in, const int* in_sizes, int n_in,
                              void* d_out, int out_size)
{
    const float* hs   = (const float*)d_in[0];
    const float* ctx  = (const float*)d_in[1];
    const float* wq1  = (const float*)d_in[2];
    const float* wk1  = (const float*)d_in[3];
    const float* wv1  = (const float*)d_in[4];
    const float* wo1  = (const float*)d_in[5];
    const float* bo1  = (const float*)d_in[6];
    const float* wq2  = (const float*)d_in[7];
    const float* wk2  = (const float*)d_in[8];
    const float* wv2  = (const float*)d_in[9];
    const float* wo2  = (const float*)d_in[10];
    const float* bo2  = (const float*)d_in[11];
    const float* wff1 = (const float*)d_in[12];
    const float* bff1 = (const float*)d_in[13];
    const float* wff2 = (const float*)d_in[14];
    const float* bff2 = (const float*)d_in[15];
    const float* ln1g = (const float*)d_in[16];
    const float* ln1b = (const float*)d_in[17];
    const float* ln2g = (const float*)d_in[18];
    const float* ln2b = (const float*)d_in[19];
    const float* ln3g = (const float*)d_in[20];
    const float* ln3b = (const float*)d_in[21];
    float* out = (float*)d_out;

    __half *xn, *q, *k, *v, *ah, *gg, *wh;
    float *h, *bf1;
    cudaGetSymbolAddress((void**)&xn,  g_xnh);
    cudaGetSymbolAddress((void**)&q,   g_qh);
    cudaGetSymbolAddress((void**)&k,   g_kh);
    cudaGetSymbolAddress((void**)&v,   g_vh);
    cudaGetSymbolAddress((void**)&ah,  g_ah);
    cudaGetSymbolAddress((void**)&gg,  g_ggh);
    cudaGetSymbolAddress((void**)&wh,  g_wh);
    cudaGetSymbolAddress((void**)&h,   g_h);
    cudaGetSymbolAddress((void**)&bf1, g_bf1);

    static bool init_done = false;
    static cudaStream_t s2;
    static cudaEvent_t evRoot, evE, evL, evAT, evKV;
    if (!init_done) {
        cudaFuncSetAttribute(gemm_h, cudaFuncAttributeMaxDynamicSharedMemorySize, GEMM_SMEM);
        cudaFuncSetAttribute(attn_h, cudaFuncAttributeMaxDynamicSharedMemorySize, ATTN_SMEM);
        cudaStreamCreateWithFlags(&s2, cudaStreamNonBlocking);
        cudaEventCreateWithFlags(&evRoot, cudaEventDisableTiming);
        cudaEventCreateWithFlags(&evE,    cudaEventDisableTiming);
        cudaEventCreateWithFlags(&evL,    cudaEventDisableTiming);
        cudaEventCreateWithFlags(&evAT,   cudaEventDisableTiming);
        cudaEventCreateWithFlags(&evKV,   cudaEventDisableTiming);
        init_done = true;
    }

    // ---- weight-conversion job tables ----
    CJobs cjE;
    {
        const float* s[3] = {wq1, wk1, wv1};
        const int    o[3] = {OWQ1, OWK1, OWV1};
        for (int i = 0; i < 3; i++) {
            cjE.src[i] = s[i]; cjE.dst[i] = wh + o[i]; cjE.n[i] = 1048576;
            cjE.scale[i] = (i == 0) ? 0.125f : 1.0f;
        }
        // pad unused
        for (int i = 3; i < 6; i++) { cjE.src[i] = s[0]; cjE.dst[i] = wh; cjE.n[i] = 0; cjE.scale[i] = 1.f; }
    }
    CJobs cjL;
    {
        const float* s[6] = {wo1, wq2, wk2, wv2, wo2, ctx};
        const int    o[6] = {OWO1, OWQ2, OWK2, OWV2, OWO2, OCTX};
        const int    n[6] = {1048576, 1048576, 786432, 786432, 1048576, 236544};
        for (int i = 0; i < 6; i++) {
            cjL.src[i] = s[i]; cjL.dst[i] = wh + o[i]; cjL.n[i] = n[i];
            cjL.scale[i] = (i == 1) ? 0.125f : 1.0f;
        }
    }

    const dim3 blk(256);
    const dim3 ablk(128);
    const dim3 g_attng(SEQ / 128, NHEADS, 4);
    const dim3 lngrid(BROWS / 2);

    GemmB gqkv{}, gwo1{}, gq2{}, gkv2{}, gwo2{}, gff1{}, gff2{};
    gqkv.W[0] = wh + OWQ1; gqkv.Ch[0] = q;
    gqkv.W[1] = wh + OWK1; gqkv.Ch[1] = k;
    gqkv.W[2] = wh + OWV1; gqkv.Ch[2] = v;
    gwo1.W[0] = wh + OWO1; gwo1.bias[0] = bo1; gwo1.res[0] = hs; gwo1.Cf[0] = h;
    gq2.W[0]  = wh + OWQ2; gq2.Ch[0]  = q;
    gkv2.W[0] = wh + OWK2; gkv2.Ch[0] = k;
    gkv2.W[1] = wh + OWV2; gkv2.Ch[1] = v;
    gwo2.W[0] = wh + OWO2; gwo2.bias[0] = bo2; gwo2.res[0] = h; gwo2.Cf[0] = h;
    gff1.W[0] = wh + OWF1; gff1.bias[0] = bf1; gff1.Ch[0] = gg;
    gff2.W[0] = wh + OWF2; gff2.bias[0] = bff2; gff2.res[0] = h; gff2.Cf[0] = out;

    // ---- fork stream 2 ----
    cudaEventRecord(evRoot, 0);
    cudaStreamWaitEvent(s2, evRoot, 0);

    conv_kernel<<<dim3(256, 3), blk, 0, s2>>>(cjE);
    cudaEventRecord(evE, s2);
    conv_kernel<<<dim3(512, 6), blk, 0, s2>>>(cjL);
    permute_ff1<<<dim3(16, 1024), blk, 0, s2>>>(wff1, wh + OWF1);
    permute_ff2<<<dim3(1, FFI), blk, 0, s2>>>(wff2, wh + OWF2);
    permute_bias_ff1<<<dim3(16), blk, 0, s2>>>(bff1, bf1);
    cudaEventRecord(evL, s2);

    // ---- main: self-attention block ----
    ln_kernel<<<lngrid, blk>>>(hs, xn, ln1g, ln1b);
    cudaStreamWaitEvent(0, evE, 0);
    gemm_h<<<dim3(8, 64, 3), blk, GEMM_SMEM>>>(xn, gqkv, BROWS, DIM, DIM, 1);
    attn_h<<<g_attng, ablk, ATTN_SMEM>>>(q, k, v, ah, SEQ, SEQ);
    cudaEventRecord(evAT, 0);

    // s2: kv2 GEMM
    cudaStreamWaitEvent(s2, evAT, 0);
    gemm_h<<<dim3(8, 3, 2), blk, GEMM_SMEM, s2>>>(wh + OCTX, gkv2, CROWS, DIM, CTXD, 1);
    cudaEventRecord(evKV, s2);

    // main: WO1 + cross-attention chain
    cudaStreamWaitEvent(0, evL, 0);
    gemm_h<<<dim3(8, 64, 1), blk, GEMM_SMEM>>>(ah, gwo1, BROWS, DIM, DIM, 0);
    ln_kernel<<<lngrid, blk>>>(h, xn, ln2g, ln2b);
    gemm_h<<<dim3(8, 64, 1), blk, GEMM_SMEM>>>(xn, gq2, BROWS, DIM, DIM, 1);
    cudaStreamWaitEvent(0, evKV, 0);
    attn_h<<<g_attng, ablk, ATTN_SMEM>>>(q, k, v, ah, SEQ, TCTX);
    gemm_h<<<dim3(8, 64, 1), blk, GEMM_SMEM>>>(ah, gwo2, BROWS, DIM, DIM, 0);

    // ---- GEGLU feed-forward (fused into FF1 epilogue, packed gg layout) ----
    ln_kernel<<<lngrid, blk>>>(h, xn, ln3g, ln3b);
    gemm_h<<<dim3(64, 64, 1), blk, GEMM_SMEM>>>(xn, gff1, BROWS, 2 * FFI, DIM, 2);
    gemm_h<<<dim3(8, 64, 1), blk, GEMM_SMEM>>>(gg, gff2, BROWS, DIM, FFI, 0);
}

// round 14
// speedup vs baseline: 1.1942x; 1.0048x over previous
#include <cuda_runtime.h>
#include <cuda_fp16.h>
#include <cstdint>
#include <cstddef>

// ---------------------------------------------------------------------------
#define BROWS   8192
#define CROWS   308
#define DIM     1024
#define CTXD    768
#define FFI     4096
#define SEQ     2048
#define TCTX    77
#define NHEADS  16
#define DHEAD   64

// ---------------------------------------------------------------------------
// Scratch
// ---------------------------------------------------------------------------
__device__ __half g_xnh[(size_t)BROWS * DIM];
__device__ __half g_qh [(size_t)BROWS * DIM];
__device__ __half g_kh [(size_t)BROWS * DIM];
__device__ __half g_vh [(size_t)BROWS * DIM];
__device__ __half g_ah [(size_t)BROWS * DIM];
__device__ __half g_ggh[(size_t)BROWS * FFI];
__device__ float  g_h  [(size_t)BROWS * DIM];

// half weights + context; wff1 column-interleaved (lin,gate); wff2 row-permuted
#define OWQ1 0
#define OWK1 1048576
#define OWV1 2097152
#define OWO1 3145728
#define OWQ2 4194304
#define OWK2 5242880
#define OWV2 6029312
#define OWO2 6815744
#define OWF1 7864320
#define OWF2 16252928
#define OCTX 20447232
#define WHTOT 20683776
__device__ __half g_wh[WHTOT];
__device__ float  g_bf1[2 * FFI];   // permuted FF1 bias (fp32)

// ---------------------------------------------------------------------------
// helpers
// ---------------------------------------------------------------------------
__device__ __forceinline__ void mma_h(float c[4], const unsigned a[4], const unsigned b[2]) {
    asm volatile(
        "mma.sync.aligned.m16n8k16.row.col.f32.f16.f16.f32 "
        "{%0,%1,%2,%3}, {%4,%5,%6,%7}, {%8,%9}, {%0,%1,%2,%3};\n"
        : "+f"(c[0]), "+f"(c[1]), "+f"(c[2]), "+f"(c[3])
        : "r"(a[0]), "r"(a[1]), "r"(a[2]), "r"(a[3]), "r"(b[0]), "r"(b[1]));
}
__device__ __forceinline__ void ldsm_x4(unsigned r[4], uint32_t addr) {
    asm volatile("ldmatrix.sync.aligned.m8n8.x4.shared.b16 {%0,%1,%2,%3}, [%4];"
                 : "=r"(r[0]), "=r"(r[1]), "=r"(r[2]), "=r"(r[3]) : "r"(addr));
}
__device__ __forceinline__ void ldsm_x4_t(unsigned r[4], uint32_t addr) {
    asm volatile("ldmatrix.sync.aligned.m8n8.x4.trans.shared.b16 {%0,%1,%2,%3}, [%4];"
                 : "=r"(r[0]), "=r"(r[1]), "=r"(r[2]), "=r"(r[3]) : "r"(addr));
}
__device__ __forceinline__ void cpa16(uint32_t dst, const void* src, bool pred) {
    int sz = pred ? 16 : 0;
    asm volatile("cp.async.cg.shared.global [%0], [%1], 16, %2;\n"
                 :: "r"(dst), "l"(src), "r"(sz));
}
__device__ __forceinline__ void cpa_commit() { asm volatile("cp.async.commit_group;"); }
template<int N> __device__ __forceinline__ void cpa_wait() {
    asm volatile("cp.async.wait_group %0;" :: "n"(N));
}
__device__ __forceinline__ float tanh_fast(float x) {
    float y; asm("tanh.approx.f32 %0, %1;" : "=f"(y) : "f"(x));
    return y;
}
__device__ __forceinline__ float gelu_tanh(float x) {
    const float x3 = x * x * x;
    return 0.5f * x * (1.f + tanh_fast(0.7978845608028654f * (x + 0.044715f * x3)));
}
__device__ __forceinline__ unsigned pack2(float a, float b) {
    __half2 h = __floats2half2_rn(a, b);
    return *reinterpret_cast<unsigned*>(&h);
}

// ---------------------------------------------------------------------------
// fp32 -> fp16 conversion pass (scale folds 0.125 into wq)
// ---------------------------------------------------------------------------
struct CJobs { const float* src[6]; __half* dst[6]; int n[6]; float scale[6]; };

__global__ __launch_bounds__(256) void conv_kernel(CJobs j) {
    const int job = blockIdx.y;
    const float* s = j.src[job];
    __half* d = j.dst[job];
    const int n = j.n[job];
    const float sc = j.scale[job];
    for (int i = (blockIdx.x * 256 + threadIdx.x) * 4; i < n; i += gridDim.x * 1024) {
        float4 v = *reinterpret_cast<const float4*>(s + i);
        uint2 u;
        u.x = pack2(v.x * sc, v.y * sc);
        u.y = pack2(v.z * sc, v.w * sc);
        *reinterpret_cast<uint2*>(d + i) = u;
    }
}

// Interleave wff1 columns: dst[k][2j]=lin col j, dst[k][2j+1]=gate col (j+FFI)
__global__ __launch_bounds__(256) void permute_ff1(
    const float* __restrict__ s, __half* __restrict__ d)
{
    const int k = blockIdx.y;
    const int j = blockIdx.x * 256 + threadIdx.x;
    const float lin = s[(size_t)k * (2 * FFI) + j];
    const float gt  = s[(size_t)k * (2 * FFI) + FFI + j];
    unsigned u = pack2(lin, gt);
    *reinterpret_cast<unsigned*>(d + (size_t)k * (2 * FFI) + 2 * j) = u;
}

__global__ __launch_bounds__(256) void permute_bias_ff1(
    const float* __restrict__ s, float* __restrict__ d)
{
    const int j = blockIdx.x * 256 + threadIdx.x;
    float2 v; v.x = s[j]; v.y = s[FFI + j];
    *reinterpret_cast<float2*>(d + 2 * j) = v;
}

// wff2 row permutation matching gg's packed-store column order:
// phi(p): within each 16-row group, (a,b) -> (b,a) on p = G*16 + a*4 + b.
__global__ __launch_bounds__(256) void permute_ff2(
    const float* __restrict__ s, __half* __restrict__ d)
{
    const int p = blockIdx.y;
    const int src_row = (p & ~15) | ((p & 3) << 2) | ((p >> 2) & 3);
    const int c = (blockIdx.x * 256 + threadIdx.x) * 4;
    const float4 v = *reinterpret_cast<const float4*>(s + (size_t)src_row * DIM + c);
    uint2 u;
    u.x = pack2(v.x, v.y);
    u.y = pack2(v.z, v.w);
    *reinterpret_cast<uint2*>(d + (size_t)p * DIM + c) = u;
}

// ---------------------------------------------------------------------------
// LayerNorm v2: 2 rows per block, 128 threads/row (8 elems/thread).
// ---------------------------------------------------------------------------
__global__ __launch_bounds__(256) void ln_kernel(
    const float* __restrict__ x, __half* __restrict__ y,
    const float* __restrict__ gam, const float* __restrict__ bet)
{
    __shared__ float red[2][10];
    const int half = threadIdx.x >> 7;
    const int lt   = threadIdx.x & 127;
    const int row  = blockIdx.x * 2 + half;
    const int wid  = lt >> 5, lid = lt & 31;

    const float4 xv0 = reinterpret_cast<const float4*>(x + (size_t)row * DIM)[lt * 2];
    const float4 xv1 = reinterpret_cast<const float4*>(x + (size_t)row * DIM)[lt * 2 + 1];

    float s  = xv0.x + xv0.y + xv0.z + xv0.w + xv1.x + xv1.y + xv1.z + xv1.w;
    float sq = xv0.x*xv0.x + xv0.y*xv0.y + xv0.z*xv0.z + xv0.w*xv0.w
             + xv1.x*xv1.x + xv1.y*xv1.y + xv1.z*xv1.z + xv1.w*xv1.w;
    #pragma unroll
    for (int w = 16; w > 0; w >>= 1) {
        s  += __shfl_xor_sync(0xffffffffu, s,  w);
        sq += __shfl_xor_sync(0xffffffffu, sq, w);
    }
    if (lid == 0) { red[half][wid] = s; red[half][4 + wid] = sq; }
    __syncthreads();
    if (lt < 32) {
        float a  = (lid < 4) ? red[half][lid]     : 0.f;
        float aq = (lid < 4) ? red[half][4 + lid] : 0.f;
        #pragma unroll
        for (int w = 2; w > 0; w >>= 1) {
            a  += __shfl_xor_sync(0xffffffffu, a,  w);
            aq += __shfl_xor_sync(0xffffffffu, aq, w);
        }
        if (lid == 0) { red[half][8] = a; red[half][9] = aq; }
    }
    __syncthreads();
    const float mean = red[half][8] * (1.f / DIM);
    const float var  = red[half][9] * (1.f / DIM) - mean * mean;
    const float inv  = rsqrtf(var + 1e-5f);

    const float4 gv0 = reinterpret_cast<const float4*>(gam)[lt * 2];
    const float4 gv1 = reinterpret_cast<const float4*>(gam)[lt * 2 + 1];
    const float4 bv0 = reinterpret_cast<const float4*>(bet)[lt * 2];
    const float4 bv1 = reinterpret_cast<const float4*>(bet)[lt * 2 + 1];
    uint4 u;
    u.x = pack2((xv0.x - mean) * inv * gv0.x + bv0.x, (xv0.y - mean) * inv * gv0.y + bv0.y);
    u.y = pack2((xv0.z - mean) * inv * gv0.z + bv0.z, (xv0.w - mean) * inv * gv0.w + bv0.w);
    u.z = pack2((xv1.x - mean) * inv * gv1.x + bv1.x, (xv1.y - mean) * inv * gv1.y + bv1.y);
    u.w = pack2((xv1.z - mean) * inv * gv1.z + bv1.z, (xv1.w - mean) * inv * gv1.w + bv1.w);
    *reinterpret_cast<uint4*>(y + (size_t)row * DIM + lt * 8) = u;
}

// ---------------------------------------------------------------------------
// fp16 GEMM: 128x128 CTA, 8 warps (2x4), warp tile 64x32, k-chunk 64,
// 3-stage cp.async, occ 2. ONE barrier per k-iteration.
// mode 0: fp32 store (+bias,+res). mode 1: psi-packed fp16 store (no bias).
// mode 2: GEGLU phi-packed pairs -> Ch FFI-wide.
// psi note (mode 1): packed col group holds true col psi(c); consumers
// (attention) see Q,K both psi-permuted (scores invariant) and V psi-permuted
// (cancelled by the psi-packed attention epilogue).
// ---------------------------------------------------------------------------
struct GemmB {
    const __half* W[3];
    const float* bias[3];
    const float* res[3];
    float* Cf[3];
    __half* Ch[3];
};

#define NSTG 3
#define AS_B 16384
#define BS_B 16384
#define GEMM_SMEM (NSTG * (AS_B + BS_B))   // 98304

__global__ __launch_bounds__(256, 2) void gemm_h(
    const __half* __restrict__ A, GemmB gb, int M, int N, int K, int mode)
{
    extern __shared__ char smc[];
    const int z = blockIdx.z;
    const __half* W   = gb.W[z];
    const float* bias = gb.bias[z];
    const float* res  = gb.res[z];
    float* Cf         = gb.Cf[z];
    __half* Ch        = gb.Ch[z];

    const int tid = threadIdx.x, warp = tid >> 5, lane = tid & 31;
    const int grp = lane >> 2, tig = lane & 3;
    const int wm = (warp & 1) * 64, wn = (warp >> 1) * 32;
    const int m0 = blockIdx.y << 7, n0 = blockIdx.x << 7;

    const uint32_t smem_u = (uint32_t)__cvta_generic_to_shared(smc);

    auto issue = [&](int ch, int slot) {
        const int k0 = ch << 6;
        const uint32_t ab = smem_u + slot * AS_B;
        #pragma unroll
        for (int i = 0; i < 4; i++) {
            const int idx = tid + i * 256;
            const int row = idx >> 3, c = idx & 7;
            int gr = m0 + row; if (gr >= M) gr = M - 1;
            cpa16(ab + row * 128 + ((c ^ (row & 7)) << 4),
                  A + (size_t)gr * K + k0 + c * 8, true);
        }
        const uint32_t bb = smem_u + NSTG * AS_B + slot * BS_B;
        #pragma unroll
        for (int i = 0; i < 4; i++) {
            const int idx = tid + i * 256;
            const int row = idx >> 4, c = idx & 15;
            cpa16(bb + row * 256 + ((c ^ (row & 7)) << 4),
                  W + (size_t)(k0 + row) * N + n0 + c * 8, true);
        }
        cpa_commit();
    };

    float acc[4][4][4];
    #pragma unroll
    for (int i = 0; i < 4; i++)
        #pragma unroll
        for (int j = 0; j < 4; j++)
            #pragma unroll
            for (int r = 0; r < 4; r++) acc[i][j][r] = 0.f;

    const int nch = K >> 6;
    issue(0, 0); issue(1, 1);

    for (int it = 0; it < nch; it++) {
        if (it + 1 < nch) cpa_wait<1>(); else cpa_wait<0>();
        __syncthreads();
        if (it + 2 < nch) issue(it + 2, (it + 2) % 3);

        const int slot = it % 3;
        const uint32_t ab = smem_u + slot * AS_B;
        const uint32_t bb = smem_u + NSTG * AS_B + slot * BS_B;

        #pragma unroll
        for (int ks = 0; ks < 4; ks++) {
            unsigned a[4][4];
            #pragma unroll
            for (int mi = 0; mi < 4; mi++) {
                const int row = wm + mi * 16 + (lane & 15);
                const int ch = ks * 2 + (lane >> 4);
                ldsm_x4(a[mi], ab + row * 128 + ((ch ^ (row & 7)) << 4));
            }
            unsigned b[2][4];
            #pragma unroll
            for (int njp = 0; njp < 2; njp++) {
                const int krow = ks * 16 + (lane & 15);
                const int cn = (wn >> 3) + njp * 2 + (lane >> 4);
                ldsm_x4_t(b[njp], bb + krow * 256 + ((cn ^ (krow & 7)) << 4));
            }
            #pragma unroll
            for (int mi = 0; mi < 4; mi++)
                #pragma unroll
                for (int njp = 0; njp < 2; njp++) {
                    mma_h(acc[mi][njp * 2 + 0], a[mi], b[njp] + 0);
                    mma_h(acc[mi][njp * 2 + 1], a[mi], b[njp] + 2);
                }
        }
        // no bottom __syncthreads — next iteration's top barrier suffices.
    }

    if (mode == 2) {
        // GEGLU epilogue, phi-packed (compensated by wff2 row permutation).
        #pragma unroll
        for (int mi = 0; mi < 4; mi++) {
            #pragma unroll
            for (int half = 0; half < 2; half++) {
                const int r = m0 + wm + mi * 16 + grp + half * 8;
                if (r >= M) continue;
                __half hout[4];
                #pragma unroll
                for (int nj = 0; nj < 4; nj++) {
                    const int c = n0 + wn + nj * 8 + tig * 2;
                    const float2 bv = *reinterpret_cast<const float2*>(bias + c);
                    const float lx = acc[mi][nj][half * 2 + 0] + bv.x;
                    const float gx = acc[mi][nj][half * 2 + 1] + bv.y;
                    hout[nj] = __float2half_rn(lx * gelu_tanh(gx));
                }
                const int p0 = (n0 >> 1) + (wn >> 1) + tig * 4;
                *reinterpret_cast<uint2*>(Ch + (size_t)r * FFI + p0) =
                    *reinterpret_cast<uint2*>(hout);
            }
        }
    } else if (mode == 1) {
        // psi-packed fp16 store: thread's 4 pairs (nj=0..3) -> one uint4 at
        // col n0 + wn + tig*8. No bias on this path (q/k/v, q2, kv2).
        #pragma unroll
        for (int mi = 0; mi < 4; mi++) {
            #pragma unroll
            for (int half = 0; half < 2; half++) {
                const int r = m0 + wm + mi * 16 + grp + half * 8;
                if (r >= M) continue;
                unsigned up[4];
                #pragma unroll
                for (int nj = 0; nj < 4; nj++)
                    up[nj] = pack2(acc[mi][nj][half * 2 + 0], acc[mi][nj][half * 2 + 1]);
                *reinterpret_cast<uint4*>(Ch + (size_t)r * N + n0 + wn + tig * 8) =
                    *reinterpret_cast<uint4*>(up);
            }
        }
    } else {
        #pragma unroll
        for (int mi = 0; mi < 4; mi++) {
            #pragma unroll
            for (int half = 0; half < 2; half++) {
                const int r = m0 + wm + mi * 16 + grp + half * 8;
                if (r >= M) continue;
                #pragma unroll
                for (int nj = 0; nj < 4; nj++) {
                    const int c = n0 + wn + nj * 8 + tig * 2;
                    float2 v;
                    v.x = acc[mi][nj][half * 2 + 0];
                    v.y = acc[mi][nj][half * 2 + 1];
                    if (bias) { v.x += bias[c]; v.y += bias[c + 1]; }
                    if (res) {
                        const float2 rv =
                            *reinterpret_cast<const float2*>(res + (size_t)r * N + c);
                        v.x += rv.x; v.y += rv.y;
                    }
                    *reinterpret_cast<float2*>(Cf + (size_t)r * N + c) = v;
                }
            }
        }
    }
}

// ---------------------------------------------------------------------------
// fp16 flash attention: 4 warps, 128 q/CTA, 32 q/warp (2 m16 tiles).
// 128-key smem tiles (two 64-key sub-tiles per barrier), double buffered.
// Inputs psi-permuted (Q,K cancel in scores; V's psi is cancelled by the
// psi-packed output epilogue -> stored O is in TRUE column order).
// smem 80KB, occ 2.
// ---------------------------------------------------------------------------
#define ATTN_SMEM 81920

__global__ __launch_bounds__(128, 2) void attn_h(
    const __half* __restrict__ Q, const __half* __restrict__ K,
    const __half* __restrict__ V, __half* __restrict__ O, int Sq, int Sk)
{
    extern __shared__ char smc[];
    const int tid = threadIdx.x, warp = tid >> 5, lane = tid & 31;
    const int grp = lane >> 2, tig = lane & 3;
    const int h = blockIdx.y, b = blockIdx.z;
    const int q0 = blockIdx.x * 128;
    const size_t qoff = (size_t)b * Sq * DIM + (size_t)h * DHEAD;
    const size_t koff = (size_t)b * Sk * DIM + (size_t)h * DHEAD;
    const int rbase = warp * 32;

    const uint32_t smem_u = (uint32_t)__cvta_generic_to_shared(smc);

    auto issue_kv = [&](int kt, int slot) {
        const uint32_t kb = smem_u + 16384 + slot * 32768;
        #pragma unroll
        for (int i = 0; i < 8; i++) {
            const int c = tid + i * 128;
            const int row = c >> 3, nc = c & 7;
            const int gr = kt * 128 + row;
            const bool ok = gr < Sk;
            const int grc = ok ? gr : 0;
            cpa16(kb + row * 128 + ((nc ^ (row & 7)) << 4),
                  K + koff + (size_t)grc * DIM + nc * 8, ok);
        }
        const uint32_t vb = kb + 16384;
        #pragma unroll
        for (int i = 0; i < 8; i++) {
            const int c = tid + i * 128;
            const int row = c >> 3, nc = c & 7;
            const int gr = kt * 128 + row;
            const bool ok = gr < Sk;
            const int grc = ok ? gr : 0;
            cpa16(vb + row * 128 + ((nc ^ (row & 7)) << 4),
                  V + koff + (size_t)grc * DIM + nc * 8, ok);
        }
        cpa_commit();
    };

    #pragma unroll
    for (int i = 0; i < 8; i++) {
        const int c = tid + i * 128;
        const int row = c >> 3, nc = c & 7;
        cpa16(smem_u + row * 128 + ((nc ^ (row & 7)) << 4),
              Q + qoff + (size_t)(q0 + row) * DIM + nc * 8, true);
    }
    cpa_commit();
    issue_kv(0, 0);

    unsigned qa[2][4][4];
    float o[2][8][4];
    #pragma unroll
    for (int t = 0; t < 2; t++)
        #pragma unroll
        for (int d = 0; d < 8; d++)
            #pragma unroll
            for (int r = 0; r < 4; r++) o[t][d][r] = 0.f;
    float mxA[2] = {-1e30f, -1e30f}, mxB[2] = {-1e30f, -1e30f};
    float lA[2] = {0.f, 0.f}, lB[2] = {0.f, 0.f};

    const int nkt = (Sk + 127) >> 7;
    for (int kt = 0; kt < nkt; kt++) {
        cpa_wait<0>();
        __syncthreads();
        if (kt + 1 < nkt) issue_kv(kt + 1, (kt + 1) & 1);

        if (kt == 0) {
            #pragma unroll
            for (int t = 0; t < 2; t++)
                #pragma unroll
                for (int ks = 0; ks < 4; ks++) {
                    const int row = rbase + t * 16 + (lane & 15);
                    const int ch = ks * 2 + (lane >> 4);
                    ldsm_x4(qa[t][ks], smem_u + row * 128 + ((ch ^ (row & 7)) << 4));
                }
        }

        const uint32_t kvb = smem_u + 16384 + (kt & 1) * 32768;

        #pragma unroll
        for (int hf = 0; hf < 2; hf++) {
            const uint32_t ksl = kvb + hf * 8192;
            const uint32_t vsl = kvb + 16384 + hf * 8192;
            const int jb = kt * 128 + hf * 64;

            float sc[2][8][4];
            #pragma unroll
            for (int t = 0; t < 2; t++)
                #pragma unroll
                for (int nj = 0; nj < 8; nj++)
                    #pragma unroll
                    for (int r = 0; r < 4; r++) sc[t][nj][r] = 0.f;

            #pragma unroll
            for (int ks = 0; ks < 4; ks++) {
                #pragma unroll
                for (int njp = 0; njp < 4; njp++) {
                    unsigned kb[4];
                    const int nrow = njp * 16 + (lane & 7) + (lane >> 4) * 8;
                    const int kc = ks * 2 + ((lane >> 3) & 1);
                    ldsm_x4(kb, ksl + nrow * 128 + ((kc ^ (nrow & 7)) << 4));
                    #pragma unroll
                    for (int t = 0; t < 2; t++) {
                        mma_h(sc[t][njp * 2 + 0], qa[t][ks], kb + 0);
                        mma_h(sc[t][njp * 2 + 1], qa[t][ks], kb + 2);
                    }
                }
            }

            if (jb + 64 > Sk) {
                #pragma unroll
                for (int t = 0; t < 2; t++)
                    #pragma unroll
                    for (int nj = 0; nj < 8; nj++) {
                        const int j = jb + nj * 8 + tig * 2;
                        if (j     >= Sk) { sc[t][nj][0] = -1e30f; sc[t][nj][2] = -1e30f; }
                        if (j + 1 >= Sk) { sc[t][nj][1] = -1e30f; sc[t][nj][3] = -1e30f; }
                    }
            }

            #pragma unroll
            for (int t = 0; t < 2; t++) {
                float tm0 = -1e30f, tm1 = -1e30f;
                #pragma unroll
                for (int nj = 0; nj < 8; nj++) {
                    tm0 = fmaxf(tm0, fmaxf(sc[t][nj][0], sc[t][nj][1]));
                    tm1 = fmaxf(tm1, fmaxf(sc[t][nj][2], sc[t][nj][3]));
                }
                tm0 = fmaxf(tm0, __shfl_xor_sync(0xffffffffu, tm0, 1));
                tm0 = fmaxf(tm0, __shfl_xor_sync(0xffffffffu, tm0, 2));
                tm1 = fmaxf(tm1, __shfl_xor_sync(0xffffffffu, tm1, 1));
                tm1 = fmaxf(tm1, __shfl_xor_sync(0xffffffffu, tm1, 2));
                const float mn0 = fmaxf(mxA[t], tm0), mn1 = fmaxf(mxB[t], tm1);
                const float c0 = __expf(mxA[t] - mn0), c1 = __expf(mxB[t] - mn1);
                mxA[t] = mn0; mxB[t] = mn1;
                float s0 = 0.f, s1 = 0.f;
                #pragma unroll
                for (int nj = 0; nj < 8; nj++) {
                    sc[t][nj][0] = __expf(sc[t][nj][0] - mn0);
                    sc[t][nj][1] = __expf(sc[t][nj][1] - mn0);
                    sc[t][nj][2] = __expf(sc[t][nj][2] - mn1);
                    sc[t][nj][3] = __expf(sc[t][nj][3] - mn1);
                    s0 += sc[t][nj][0] + sc[t][nj][1];
                    s1 += sc[t][nj][2] + sc[t][nj][3];
                }
                s0 += __shfl_xor_sync(0xffffffffu, s0, 1);
                s0 += __shfl_xor_sync(0xffffffffu, s0, 2);
                s1 += __shfl_xor_sync(0xffffffffu, s1, 1);
                s1 += __shfl_xor_sync(0xffffffffu, s1, 2);
                lA[t] = lA[t] * c0 + s0;
                lB[t] = lB[t] * c1 + s1;
                #pragma unroll
                for (int d = 0; d < 8; d++) {
                    o[t][d][0] *= c0; o[t][d][1] *= c0;
                    o[t][d][2] *= c1; o[t][d][3] *= c1;
                }
            }

            #pragma unroll
            for (int t = 0; t < 2; t++)
                #pragma unroll
                for (int nj = 0; nj < 8; nj++) {
                    const int r0 = rbase + t * 16 + grp;
                    *reinterpret_cast<unsigned*>(smc + r0 * 128 +
                        ((nj ^ (r0 & 7)) << 4) + tig * 4) = pack2(sc[t][nj][0], sc[t][nj][1]);
                    const int r1 = r0 + 8;
                    *reinterpret_cast<unsigned*>(smc + r1 * 128 +
                        ((nj ^ (r1 & 7)) << 4) + tig * 4) = pack2(sc[t][nj][2], sc[t][nj][3]);
                }
            __syncwarp();

            #pragma unroll
            for (int kj = 0; kj < 4; kj++) {
                unsigned pa[2][4];
                #pragma unroll
                for (int t = 0; t < 2; t++) {
                    const int row = rbase + t * 16 + (lane & 15);
                    const int ch = kj * 2 + (lane >> 4);
                    ldsm_x4(pa[t], smem_u + row * 128 + ((ch ^ (row & 7)) << 4));
                }
                #pragma unroll
                for (int dgp = 0; dgp < 4; dgp++) {
                    unsigned vb[4];
                    const int vrow = kj * 16 + (lane & 15);
                    const int vc = dgp * 2 + (lane >> 4);
                    ldsm_x4_t(vb, vsl + vrow * 128 + ((vc ^ (vrow & 7)) << 4));
                    #pragma unroll
                    for (int t = 0; t < 2; t++) {
                        mma_h(o[t][dgp * 2 + 0], pa[t], vb + 0);
                        mma_h(o[t][dgp * 2 + 1], pa[t], vb + 2);
                    }
                }
            }
            __syncwarp();
        }
    }

    // psi-packed epilogue: register pair (d, tig) -> packed col g*32 + tig*8 + (d%4)*2.
    // Cancels V's psi permutation -> stored O is in TRUE column order.
    #pragma unroll
    for (int t = 0; t < 2; t++) {
        const float i0 = 1.f / lA[t], i1 = 1.f / lB[t];
        const int row0 = q0 + rbase + t * 16 + grp;
        unsigned u[4];
        #pragma unroll
        for (int g = 0; g < 2; g++) {
            #pragma unroll
            for (int d = 0; d < 4; d++)
                u[d] = pack2(o[t][g * 4 + d][0] * i0, o[t][g * 4 + d][1] * i0);
            *reinterpret_cast<uint4*>(O + qoff + (size_t)row0 * DIM + g * 32 + tig * 8) =
                *reinterpret_cast<uint4*>(u);
            #pragma unroll
            for (int d = 0; d < 4; d++)
                u[d] = pack2(o[t][g * 4 + d][2] * i1, o[t][g * 4 + d][3] * i1);
            *reinterpret_cast<uint4*>(O + qoff + (size_t)(row0 + 8) * DIM + g * 32 + tig * 8) =
                *reinterpret_cast<uint4*>(u);
        }
    }
}

// ---------------------------------------------------------------------------
extern "C" void kernel_launch(void* const* d_in, const int* in_sizes, int n_in,
                              void* d_out, int out_size)
{
    const float* hs   = (const float*)d_in[0];
    const float* ctx  = (const float*)d_in[1];
    const float* wq1  = (const float*)d_in[2];
    const float* wk1  = (const float*)d_in[3];
    const float* wv1  = (const float*)d_in[4];
    const float* wo1  = (const float*)d_in[5];
    const float* bo1  = (const float*)d_in[6];
    const float* wq2  = (const float*)d_in[7];
    const float* wk2  = (const float*)d_in[8];
    const float* wv2  = (const float*)d_in[9];
    const float* wo2  = (const float*)d_in[10];
    const float* bo2  = (const float*)d_in[11];
    const float* wff1 = (const float*)d_in[12];
    const float* bff1 = (const float*)d_in[13];
    const float* wff2 = (const float*)d_in[14];
    const float* bff2 = (const float*)d_in[15];
    const float* ln1g = (const float*)d_in[16];
    const float* ln1b = (const float*)d_in[17];
    const float* ln2g = (const float*)d_in[18];
    const float* ln2b = (const float*)d_in[19];
    const float* ln3g = (const float*)d_in[20];
    const float* ln3b = (const float*)d_in[21];
    float* out = (float*)d_out;

    __half *xn, *q, *k, *v, *ah, *gg, *wh;
    float *h, *bf1;
    cudaGetSymbolAddress((void**)&xn,  g_xnh);
    cudaGetSymbolAddress((void**)&q,   g_qh);
    cudaGetSymbolAddress((void**)&k,   g_kh);
    cudaGetSymbolAddress((void**)&v,   g_vh);
    cudaGetSymbolAddress((void**)&ah,  g_ah);
    cudaGetSymbolAddress((void**)&gg,  g_ggh);
    cudaGetSymbolAddress((void**)&wh,  g_wh);
    cudaGetSymbolAddress((void**)&h,   g_h);
    cudaGetSymbolAddress((void**)&bf1, g_bf1);

    static bool init_done = false;
    static cudaStream_t s2;
    static cudaEvent_t evRoot, evE, evL, evAT, evKV;
    if (!init_done) {
        cudaFuncSetAttribute(gemm_h, cudaFuncAttributeMaxDynamicSharedMemorySize, GEMM_SMEM);
        cudaFuncSetAttribute(attn_h, cudaFuncAttributeMaxDynamicSharedMemorySize, ATTN_SMEM);
        cudaStreamCreateWithFlags(&s2, cudaStreamNonBlocking);
        cudaEventCreateWithFlags(&evRoot, cudaEventDisableTiming);
        cudaEventCreateWithFlags(&evE,    cudaEventDisableTiming);
        cudaEventCreateWithFlags(&evL,    cudaEventDisableTiming);
        cudaEventCreateWithFlags(&evAT,   cudaEventDisableTiming);
        cudaEventCreateWithFlags(&evKV,   cudaEventDisableTiming);
        init_done = true;
    }

    // ---- weight-conversion job tables ----
    CJobs cjE;
    {
        const float* s[3] = {wq1, wk1, wv1};
        const int    o[3] = {OWQ1, OWK1, OWV1};
        for (int i = 0; i < 3; i++) {
            cjE.src[i] = s[i]; cjE.dst[i] = wh + o[i]; cjE.n[i] = 1048576;
            cjE.scale[i] = (i == 0) ? 0.125f : 1.0f;
        }
        for (int i = 3; i < 6; i++) { cjE.src[i] = s[0]; cjE.dst[i] = wh; cjE.n[i] = 0; cjE.scale[i] = 1.f; }
    }
    CJobs cjL;
    {
        const float* s[6] = {wo1, wq2, wk2, wv2, wo2, ctx};
        const int    o[6] = {OWO1, OWQ2, OWK2, OWV2, OWO2, OCTX};
        const int    n[6] = {1048576, 1048576, 786432, 786432, 1048576, 236544};
        for (int i = 0; i < 6; i++) {
            cjL.src[i] = s[i]; cjL.dst[i] = wh + o[i]; cjL.n[i] = n[i];
            cjL.scale[i] = (i == 1) ? 0.125f : 1.0f;
        }
    }

    const dim3 blk(256);
    const dim3 ablk(128);
    const dim3 g_attng(SEQ / 128, NHEADS, 4);
    const dim3 lngrid(BROWS / 2);

    GemmB gqkv{}, gwo1{}, gq2{}, gkv2{}, gwo2{}, gff1{}, gff2{};
    gqkv.W[0] = wh + OWQ1; gqkv.Ch[0] = q;
    gqkv.W[1] = wh + OWK1; gqkv.Ch[1] = k;
    gqkv.W[2] = wh + OWV1; gqkv.Ch[2] = v;
    gwo1.W[0] = wh + OWO1; gwo1.bias[0] = bo1; gwo1.res[0] = hs; gwo1.Cf[0] = h;
    gq2.W[0]  = wh + OWQ2; gq2.Ch[0]  = q;
    gkv2.W[0] = wh + OWK2; gkv2.Ch[0] = k;
    gkv2.W[1] = wh + OWV2; gkv2.Ch[1] = v;
    gwo2.W[0] = wh + OWO2; gwo2.bias[0] = bo2; gwo2.res[0] = h; gwo2.Cf[0] = h;
    gff1.W[0] = wh + OWF1; gff1.bias[0] = bf1; gff1.Ch[0] = gg;
    gff2.W[0] = wh + OWF2; gff2.bias[0] = bff2; gff2.res[0] = h; gff2.Cf[0] = out;

    // ---- fork stream 2 ----
    cudaEventRecord(evRoot, 0);
    cudaStreamWaitEvent(s2, evRoot, 0);

    conv_kernel<<<dim3(256, 3), blk, 0, s2>>>(cjE);
    cudaEventRecord(evE, s2);
    conv_kernel<<<dim3(512, 6), blk, 0, s2>>>(cjL);
    permute_ff1<<<dim3(16, 1024), blk, 0, s2>>>(wff1, wh + OWF1);
    permute_ff2<<<dim3(1, FFI), blk, 0, s2>>>(wff2, wh + OWF2);
    permute_bias_ff1<<<dim3(16), blk, 0, s2>>>(bff1, bf1);
    cudaEventRecord(evL, s2);

    // ---- main: self-attention block ----
    ln_kernel<<<lngrid, blk>>>(hs, xn, ln1g, ln1b);
    cudaStreamWaitEvent(0, evE, 0);
    gemm_h<<<dim3(8, 64, 3), blk, GEMM_SMEM>>>(xn, gqkv, BROWS, DIM, DIM, 1);
    attn_h<<<g_attng, ablk, ATTN_SMEM>>>(q, k, v, ah, SEQ, SEQ);
    cudaEventRecord(evAT, 0);

    // s2: kv2 GEMM
    cudaStreamWaitEvent(s2, evAT, 0);
    gemm_h<<<dim3(8, 3, 2), blk, GEMM_SMEM, s2>>>(wh + OCTX, gkv2, CROWS, DIM, CTXD, 1);
    cudaEventRecord(evKV, s2);

    // main: WO1 + cross-attention chain
    cudaStreamWaitEvent(0, evL, 0);
    gemm_h<<<dim3(8, 64, 1), blk, GEMM_SMEM>>>(ah, gwo1, BROWS, DIM, DIM, 0);
    ln_kernel<<<lngrid, blk>>>(h, xn, ln2g, ln2b);
    gemm_h<<<dim3(8, 64, 1), blk, GEMM_SMEM>>>(xn, gq2, BROWS, DIM, DIM, 1);
    cudaStreamWaitEvent(0, evKV, 0);
    attn_h<<<g_attng, ablk, ATTN_SMEM>>>(q, k, v, ah, SEQ, TCTX);
    gemm_h<<<dim3(8, 64, 1), blk, GEMM_SMEM>>>(ah, gwo2, BROWS, DIM, DIM, 0);

    // ---- GEGLU feed-forward (fused into FF1 epilogue, packed gg layout) ----
    ln_kernel<<<lngrid, blk>>>(h, xn, ln3g, ln3b);
    gemm_h<<<dim3(64, 64, 1), blk, GEMM_SMEM>>>(xn, gff1, BROWS, 2 * FFI, DIM, 2);
    gemm_h<<<dim3(8, 64, 1), blk, GEMM_SMEM>>>(gg, gff2, BROWS, DIM, FFI, 0);
}